// round 2
// baseline (speedup 1.0000x reference)
#include <cuda_runtime.h>

constexpr int kN = 100000;
constexpr int kE = 1600000;
constexpr int kG = 2048;
constexpr int kD = 128;
constexpr int kScanBlocks = (kN + 1023) / 1024; // 98

// ---------------- scratch (no allocations allowed) ----------------
__device__ float g_bufA[kN * kD];     // 51.2 MB
__device__ float g_bufB[kN * kD];     // 51.2 MB
__device__ float g_inv_src[kN];
__device__ float g_inv_dst[kN];
__device__ int   g_deg_out[kN];
__device__ int   g_deg_in[kN];
__device__ int   g_row_ptr[kN + 1];
__device__ int   g_cursor[kN];
__device__ int   g_edge_src[kE];      // src ids grouped by dst (CSR)
__device__ int   g_blk[kScanBlocks];
__device__ float g_emb[kG * kD];
__device__ int   g_gcnt[kG];
__device__ float g_x1[kG * 512];
__device__ float g_x2[kG * 256];

// ---------------- f32x2 helpers ----------------
__device__ __forceinline__ unsigned long long ffma2(unsigned long long a,
                                                    unsigned long long b,
                                                    unsigned long long c) {
    unsigned long long d;
    asm("fma.rn.f32x2 %0, %1, %2, %3;" : "=l"(d) : "l"(a), "l"(b), "l"(c));
    return d;
}
__device__ __forceinline__ unsigned long long pack2(float lo, float hi) {
    unsigned long long d;
    asm("mov.b64 %0, {%1, %2};" : "=l"(d) : "f"(lo), "f"(hi));
    return d;
}
__device__ __forceinline__ void unpack2(unsigned long long v, float& lo, float& hi) {
    asm("mov.b64 {%0, %1}, %2;" : "=f"(lo), "=f"(hi) : "l"(v));
}

// ---------------- setup kernels ----------------
__global__ void k_zero_deg() {
    int i = blockIdx.x * blockDim.x + threadIdx.x;
    if (i < kN) { g_deg_out[i] = 0; g_deg_in[i] = 0; }
}

__global__ void k_degrees(const int* __restrict__ src, const int* __restrict__ dst) {
    int e = blockIdx.x * blockDim.x + threadIdx.x;
    if (e >= kE) return;
    atomicAdd(&g_deg_out[src[e]], 1);
    atomicAdd(&g_deg_in[dst[e]], 1);
}

__global__ void k_inv() {
    int i = blockIdx.x * blockDim.x + threadIdx.x;
    if (i >= kN) return;
    g_inv_src[i] = rsqrtf((float)max(g_deg_out[i], 1));
    g_inv_dst[i] = rsqrtf((float)max(g_deg_in[i], 1));
}

__global__ void k_scan1() {
    __shared__ int sm[1024];
    int tid = threadIdx.x;
    int i = blockIdx.x * 1024 + tid;
    int v = (i < kN) ? g_deg_in[i] : 0;
    int x = v;
    sm[tid] = x;
    __syncthreads();
    for (int off = 1; off < 1024; off <<= 1) {
        int y = (tid >= off) ? sm[tid - off] : 0;
        __syncthreads();
        x += y;
        sm[tid] = x;
        __syncthreads();
    }
    if (i < kN) g_row_ptr[i] = x - v;
    if (tid == 1023) g_blk[blockIdx.x] = x;
}

__global__ void k_scan_tops() {
    __shared__ int sm[1024];
    int tid = threadIdx.x;
    int v = (tid < kScanBlocks) ? g_blk[tid] : 0;
    int x = v;
    sm[tid] = x;
    __syncthreads();
    for (int off = 1; off < 1024; off <<= 1) {
        int y = (tid >= off) ? sm[tid - off] : 0;
        __syncthreads();
        x += y;
        sm[tid] = x;
        __syncthreads();
    }
    if (tid < kScanBlocks) g_blk[tid] = x - v;
}

__global__ void k_scan_add() {
    int i = blockIdx.x * blockDim.x + threadIdx.x;
    if (i < kN) {
        int rp = g_row_ptr[i] + g_blk[i >> 10];
        g_row_ptr[i] = rp;
        g_cursor[i]  = rp;
    }
    if (i == 0) g_row_ptr[kN] = kE;
}

__global__ void k_scatter(const int* __restrict__ src, const int* __restrict__ dst) {
    int e = blockIdx.x * blockDim.x + threadIdx.x;
    if (e >= kE) return;
    int d = dst[e];
    int pos = atomicAdd(&g_cursor[d], 1);
    g_edge_src[pos] = src[e];
}

// ---------------- fused GCN layer: gather + GEMM(+bias, ReLU) ----------------
// Block: 256 threads, 64 dst rows. Smem: Ws[128][128] + As[128 k][66 rows].
// out[row] = relu( (inv_dst[row] * sum_e inv_src[s_e] * h[s_e]) @ W + b )
constexpr int kPad = 66;
constexpr int kLayerSmemBytes = (128 * 128 + 128 * kPad) * 4; // 99328

__global__ void __launch_bounds__(256, 2)
k_layer(const float* __restrict__ h, const float* __restrict__ W,
        const float* __restrict__ b, float* __restrict__ out, int rows) {
    extern __shared__ float sm[];
    float* Ws = sm;                   // [128][128]
    float* As = sm + 128 * 128;       // [128][kPad], k-major, row index swizzled
    int t = threadIdx.x;
    int wid = t >> 5;
    int lane = t & 31;
    int row0 = blockIdx.x * 64;

    // ---- phase 1: stage W (overlaps with gather; no sync needed between) ----
    {
        const float4* W4 = reinterpret_cast<const float4*>(W);
        float4* Ws4 = reinterpret_cast<float4*>(Ws);
        #pragma unroll
        for (int i = 0; i < 16; ++i) Ws4[t + i * 256] = W4[t + i * 256];
    }

    // ---- phase 2: gather 8 rows per warp into As (k-major, swizzled) ----
    const float4* H4 = reinterpret_cast<const float4*>(h);
    int xr = ((lane >> 2) & 7) << 1;  // swizzle key = ((k>>4)&7)<<1, k = 4*lane+j
    #pragma unroll
    for (int i = 0; i < 8; ++i) {
        int rloc = wid * 8 + i;
        int grow = row0 + rloc;
        float4 acc = make_float4(0.f, 0.f, 0.f, 0.f);
        if (grow < rows) {
            int e0 = g_row_ptr[grow];
            int e1 = g_row_ptr[grow + 1];
            int e = e0;
            for (; e + 3 < e1; e += 4) {
                int s0 = g_edge_src[e + 0];
                int s1 = g_edge_src[e + 1];
                int s2 = g_edge_src[e + 2];
                int s3 = g_edge_src[e + 3];
                float4 x0 = H4[(size_t)s0 * 32 + lane];
                float4 x1 = H4[(size_t)s1 * 32 + lane];
                float4 x2 = H4[(size_t)s2 * 32 + lane];
                float4 x3 = H4[(size_t)s3 * 32 + lane];
                float w0 = g_inv_src[s0], w1 = g_inv_src[s1];
                float w2 = g_inv_src[s2], w3 = g_inv_src[s3];
                acc.x += w0 * x0.x + w1 * x1.x + w2 * x2.x + w3 * x3.x;
                acc.y += w0 * x0.y + w1 * x1.y + w2 * x2.y + w3 * x3.y;
                acc.z += w0 * x0.z + w1 * x1.z + w2 * x2.z + w3 * x3.z;
                acc.w += w0 * x0.w + w1 * x1.w + w2 * x2.w + w3 * x3.w;
            }
            for (; e < e1; ++e) {
                int s = g_edge_src[e];
                float ws = g_inv_src[s];
                float4 x = H4[(size_t)s * 32 + lane];
                acc.x += ws * x.x; acc.y += ws * x.y;
                acc.z += ws * x.z; acc.w += ws * x.w;
            }
            float wd = g_inv_dst[grow];
            acc.x *= wd; acc.y *= wd; acc.z *= wd; acc.w *= wd;
        }
        int rsw = rloc ^ xr;
        As[(4 * lane + 0) * kPad + rsw] = acc.x;
        As[(4 * lane + 1) * kPad + rsw] = acc.y;
        As[(4 * lane + 2) * kPad + rsw] = acc.z;
        As[(4 * lane + 3) * kPad + rsw] = acc.w;
    }
    __syncthreads();

    // ---- phase 3: GEMM with f32x2 FMA. 8 rows (4 pairs) x 4 cols / thread ----
    int rg = wid;               // rows rg*8 .. rg*8+7
    int cg = lane * 4;          // cols cg .. cg+3

    unsigned long long acc2[4][4];
    #pragma unroll
    for (int p = 0; p < 4; ++p)
        #pragma unroll
        for (int j = 0; j < 4; ++j) acc2[p][j] = 0ull;

    #pragma unroll 16
    for (int k = 0; k < 128; ++k) {
        float4 w4 = *reinterpret_cast<const float4*>(&Ws[k * 128 + cg]);
        unsigned long long wp0 = pack2(w4.x, w4.x);
        unsigned long long wp1 = pack2(w4.y, w4.y);
        unsigned long long wp2 = pack2(w4.z, w4.z);
        unsigned long long wp3 = pack2(w4.w, w4.w);
        int xk = ((k >> 4) & 7) << 1;
        #pragma unroll
        for (int p = 0; p < 4; ++p) {
            int r0 = rg * 8 + 2 * p;
            unsigned long long a =
                *reinterpret_cast<const unsigned long long*>(&As[k * kPad + (r0 ^ xk)]);
            acc2[p][0] = ffma2(a, wp0, acc2[p][0]);
            acc2[p][1] = ffma2(a, wp1, acc2[p][1]);
            acc2[p][2] = ffma2(a, wp2, acc2[p][2]);
            acc2[p][3] = ffma2(a, wp3, acc2[p][3]);
        }
    }

    float4 bb = *reinterpret_cast<const float4*>(&b[cg]);
    #pragma unroll
    for (int p = 0; p < 4; ++p) {
        float lo0, hi0, lo1, hi1, lo2, hi2, lo3, hi3;
        unpack2(acc2[p][0], lo0, hi0);
        unpack2(acc2[p][1], lo1, hi1);
        unpack2(acc2[p][2], lo2, hi2);
        unpack2(acc2[p][3], lo3, hi3);
        int row = row0 + rg * 8 + 2 * p;
        if (row < rows) {
            float4 o;
            o.x = fmaxf(lo0 + bb.x, 0.f);
            o.y = fmaxf(lo1 + bb.y, 0.f);
            o.z = fmaxf(lo2 + bb.z, 0.f);
            o.w = fmaxf(lo3 + bb.w, 0.f);
            *reinterpret_cast<float4*>(out + (size_t)row * 128 + cg) = o;
        }
        if (row + 1 < rows) {
            float4 o;
            o.x = fmaxf(hi0 + bb.x, 0.f);
            o.y = fmaxf(hi1 + bb.y, 0.f);
            o.z = fmaxf(hi2 + bb.z, 0.f);
            o.w = fmaxf(hi3 + bb.w, 0.f);
            *reinterpret_cast<float4*>(out + (size_t)(row + 1) * 128 + cg) = o;
        }
    }
}

// ---------------- pooling ----------------
__global__ void k_zero_pool() {
    int i = blockIdx.x * blockDim.x + threadIdx.x;
    if (i < kG * kD) g_emb[i] = 0.f;
    if (i < kG) g_gcnt[i] = 0;
}

__global__ void k_pool(const float* __restrict__ h, const int* __restrict__ gids) {
    int w = (blockIdx.x * blockDim.x + threadIdx.x) >> 5;
    int lane = threadIdx.x & 31;
    if (w >= kN) return;
    int gid = gids[w];
    float4 x = reinterpret_cast<const float4*>(h + (size_t)w * kD)[lane];
    float* e = g_emb + (size_t)gid * kD + lane * 4;
    atomicAdd(e + 0, x.x);
    atomicAdd(e + 1, x.y);
    atomicAdd(e + 2, x.z);
    atomicAdd(e + 3, x.w);
    if (lane == 0) atomicAdd(&g_gcnt[gid], 1);
}

__global__ void k_pool_norm() {
    int i = blockIdx.x * blockDim.x + threadIdx.x;
    if (i >= kG * kD) return;
    int g = i >> 7;
    float c = (float)max(g_gcnt[g], 1);
    g_emb[i] = g_emb[i] / c;
}

// ---------------- MLP head ----------------
__global__ void k_mlp(const float* __restrict__ X, const float* __restrict__ W,
                      const float* __restrict__ b, float* __restrict__ Y,
                      int K, int M) {
    int idx = blockIdx.x * blockDim.x + threadIdx.x;
    int c = idx % M;
    int g0 = (idx / M) * 8;
    if (g0 >= kG) return;
    float acc[8];
    #pragma unroll
    for (int j = 0; j < 8; ++j) acc[j] = 0.f;
    for (int k = 0; k < K; ++k) {
        float w = W[(size_t)k * M + c];
        #pragma unroll
        for (int j = 0; j < 8; ++j)
            acc[j] += X[(size_t)(g0 + j) * K + k] * w;
    }
    float bias = b[c];
    #pragma unroll
    for (int j = 0; j < 8; ++j)
        Y[(size_t)(g0 + j) * M + c] = fmaxf(acc[j] + bias, 0.f);
}

__global__ void k_final(const float* __restrict__ X, const float* __restrict__ W,
                        const float* __restrict__ b, float* __restrict__ out) {
    int g = (blockIdx.x * blockDim.x + threadIdx.x) >> 5;
    int lane = threadIdx.x & 31;
    if (g >= kG) return;
    float s = 0.f;
    #pragma unroll
    for (int k = lane; k < 256; k += 32) s += X[(size_t)g * 256 + k] * W[k];
    #pragma unroll
    for (int off = 16; off; off >>= 1) s += __shfl_down_sync(0xffffffffu, s, off);
    if (lane == 0) out[g] = s + b[0];
}

// ---------------- launch ----------------
extern "C" void kernel_launch(void* const* d_in, const int* in_sizes, int n_in,
                              void* d_out, int out_size) {
    const float* feats = (const float*)d_in[0];
    const int*   src   = (const int*)d_in[1];
    const int*   dst   = (const int*)d_in[2];
    const int*   gids  = (const int*)d_in[3];
    const float* W0 = (const float*)d_in[4];  const float* b0 = (const float*)d_in[5];
    const float* W1 = (const float*)d_in[6];  const float* b1 = (const float*)d_in[7];
    const float* W2 = (const float*)d_in[8];  const float* b2 = (const float*)d_in[9];
    const float* Wm0 = (const float*)d_in[10]; const float* bm0 = (const float*)d_in[11];
    const float* Wm1 = (const float*)d_in[12]; const float* bm1 = (const float*)d_in[13];
    const float* Wm2 = (const float*)d_in[14]; const float* bm2 = (const float*)d_in[15];
    float* out = (float*)d_out;

    float *bufA, *bufB, *emb, *x1, *x2;
    cudaGetSymbolAddress((void**)&bufA, g_bufA);
    cudaGetSymbolAddress((void**)&bufB, g_bufB);
    cudaGetSymbolAddress((void**)&emb,  g_emb);
    cudaGetSymbolAddress((void**)&x1,   g_x1);
    cudaGetSymbolAddress((void**)&x2,   g_x2);

    cudaFuncSetAttribute(k_layer, cudaFuncAttributeMaxDynamicSharedMemorySize,
                         kLayerSmemBytes);

    const int T = 256;
    int nBlkN = (kN + T - 1) / T;           // 391
    int nBlkE = (kE + T - 1) / T;           // 6250
    int nBlkWarpN = (kN * 32 + T - 1) / T;  // 12500
    int nBlkLayer = (kN + 63) / 64;         // 1563
    int nBlkPoolZ = (kG * kD + T - 1) / T;  // 1024

    // degrees + normalization coefficients
    k_zero_deg<<<nBlkN, T>>>();
    k_degrees<<<nBlkE, T>>>(src, dst);
    k_inv<<<nBlkN, T>>>();

    // CSR-by-dst build
    k_scan1<<<kScanBlocks, 1024>>>();
    k_scan_tops<<<1, 1024>>>();
    k_scan_add<<<nBlkN, T>>>();
    k_scatter<<<nBlkE, T>>>(src, dst);

    // 3 fused GCN layers (gather + GEMM + bias + ReLU)
    k_layer<<<nBlkLayer, T, kLayerSmemBytes>>>(feats, W0, b0, bufA, kN);
    k_layer<<<nBlkLayer, T, kLayerSmemBytes>>>(bufA,  W1, b1, bufB, kN);
    k_layer<<<nBlkLayer, T, kLayerSmemBytes>>>(bufB,  W2, b2, bufA, kN);

    // average pooling per graph
    k_zero_pool<<<nBlkPoolZ, T>>>();
    k_pool<<<nBlkWarpN, T>>>(bufA, gids);
    k_pool_norm<<<nBlkPoolZ, T>>>();

    // MLP head
    k_mlp<<<(kG / 8) * 512 / T, T>>>(emb, Wm0, bm0, x1, 128, 512);
    k_mlp<<<(kG / 8) * 256 / T, T>>>(x1, Wm1, bm1, x2, 512, 256);
    k_final<<<(kG * 32) / T, T>>>(x2, Wm2, bm2, out);
}

// round 3
// speedup vs baseline: 1.2214x; 1.2214x over previous
#include <cuda_runtime.h>

constexpr int kN = 100000;
constexpr int kE = 1600000;
constexpr int kG = 2048;
constexpr int kD = 128;
constexpr int kScanBlocks = (kN + 1023) / 1024; // 98

// ---------------- scratch (no allocations allowed) ----------------
__device__ float g_bufA[kN * kD];     // 51.2 MB
__device__ float g_bufB[kN * kD];     // 51.2 MB
__device__ float g_inv_src[kN];
__device__ float g_inv_dst[kN];
__device__ int   g_deg_out[kN];
__device__ int   g_deg_in[kN];
__device__ int   g_row_ptr[kN + 1];
__device__ int   g_cursor[kN];
__device__ int   g_edge_src[kE];      // src ids grouped by dst (CSR)
__device__ int   g_blk[kScanBlocks];
__device__ float g_emb[kG * kD];
__device__ int   g_gcnt[kG];
__device__ float g_x1[kG * 512];
__device__ float g_x2[kG * 256];

// ---------------- f32x2 helpers ----------------
__device__ __forceinline__ unsigned long long ffma2(unsigned long long a,
                                                    unsigned long long b,
                                                    unsigned long long c) {
    unsigned long long d;
    asm("fma.rn.f32x2 %0, %1, %2, %3;" : "=l"(d) : "l"(a), "l"(b), "l"(c));
    return d;
}
__device__ __forceinline__ unsigned long long pack2(float lo, float hi) {
    unsigned long long d;
    asm("mov.b64 %0, {%1, %2};" : "=l"(d) : "f"(lo), "f"(hi));
    return d;
}
__device__ __forceinline__ void unpack2(unsigned long long v, float& lo, float& hi) {
    asm("mov.b64 {%0, %1}, %2;" : "=f"(lo), "=f"(hi) : "l"(v));
}

// ---------------- setup kernels ----------------
__global__ void k_zero_deg() {
    int i = blockIdx.x * blockDim.x + threadIdx.x;
    if (i < kN) { g_deg_out[i] = 0; g_deg_in[i] = 0; }
}

__global__ void k_degrees(const int* __restrict__ src, const int* __restrict__ dst) {
    int e = blockIdx.x * blockDim.x + threadIdx.x;
    if (e >= kE) return;
    atomicAdd(&g_deg_out[src[e]], 1);
    atomicAdd(&g_deg_in[dst[e]], 1);
}

__global__ void k_inv() {
    int i = blockIdx.x * blockDim.x + threadIdx.x;
    if (i >= kN) return;
    g_inv_src[i] = rsqrtf((float)max(g_deg_out[i], 1));
    g_inv_dst[i] = rsqrtf((float)max(g_deg_in[i], 1));
}

__global__ void k_scan1() {
    __shared__ int sm[1024];
    int tid = threadIdx.x;
    int i = blockIdx.x * 1024 + tid;
    int v = (i < kN) ? g_deg_in[i] : 0;
    int x = v;
    sm[tid] = x;
    __syncthreads();
    for (int off = 1; off < 1024; off <<= 1) {
        int y = (tid >= off) ? sm[tid - off] : 0;
        __syncthreads();
        x += y;
        sm[tid] = x;
        __syncthreads();
    }
    if (i < kN) g_row_ptr[i] = x - v;
    if (tid == 1023) g_blk[blockIdx.x] = x;
}

__global__ void k_scan_tops() {
    __shared__ int sm[1024];
    int tid = threadIdx.x;
    int v = (tid < kScanBlocks) ? g_blk[tid] : 0;
    int x = v;
    sm[tid] = x;
    __syncthreads();
    for (int off = 1; off < 1024; off <<= 1) {
        int y = (tid >= off) ? sm[tid - off] : 0;
        __syncthreads();
        x += y;
        sm[tid] = x;
        __syncthreads();
    }
    if (tid < kScanBlocks) g_blk[tid] = x - v;
}

__global__ void k_scan_add() {
    int i = blockIdx.x * blockDim.x + threadIdx.x;
    if (i < kN) {
        int rp = g_row_ptr[i] + g_blk[i >> 10];
        g_row_ptr[i] = rp;
        g_cursor[i]  = rp;
    }
    if (i == 0) g_row_ptr[kN] = kE;
}

__global__ void k_scatter(const int* __restrict__ src, const int* __restrict__ dst) {
    int e = blockIdx.x * blockDim.x + threadIdx.x;
    if (e >= kE) return;
    int d = dst[e];
    int pos = atomicAdd(&g_cursor[d], 1);
    g_edge_src[pos] = src[e];
}

// ---------------- GCN aggregation: one warp per dst node ----------------
__global__ void k_gather(const float* __restrict__ h, float* __restrict__ m) {
    int w = (blockIdx.x * blockDim.x + threadIdx.x) >> 5;
    int lane = threadIdx.x & 31;
    if (w >= kN) return;
    int e0 = g_row_ptr[w];
    int e1 = g_row_ptr[w + 1];
    const float4* H4 = reinterpret_cast<const float4*>(h);
    float4 acc = make_float4(0.f, 0.f, 0.f, 0.f);
    int e = e0;
    for (; e + 3 < e1; e += 4) {
        int s0 = g_edge_src[e + 0];
        int s1 = g_edge_src[e + 1];
        int s2 = g_edge_src[e + 2];
        int s3 = g_edge_src[e + 3];
        float4 x0 = H4[(size_t)s0 * 32 + lane];
        float4 x1 = H4[(size_t)s1 * 32 + lane];
        float4 x2 = H4[(size_t)s2 * 32 + lane];
        float4 x3 = H4[(size_t)s3 * 32 + lane];
        float w0 = g_inv_src[s0], w1 = g_inv_src[s1];
        float w2 = g_inv_src[s2], w3 = g_inv_src[s3];
        acc.x += w0 * x0.x + w1 * x1.x + w2 * x2.x + w3 * x3.x;
        acc.y += w0 * x0.y + w1 * x1.y + w2 * x2.y + w3 * x3.y;
        acc.z += w0 * x0.z + w1 * x1.z + w2 * x2.z + w3 * x3.z;
        acc.w += w0 * x0.w + w1 * x1.w + w2 * x2.w + w3 * x3.w;
    }
    for (; e < e1; ++e) {
        int s = g_edge_src[e];
        float ws = g_inv_src[s];
        float4 x = H4[(size_t)s * 32 + lane];
        acc.x += ws * x.x; acc.y += ws * x.y;
        acc.z += ws * x.z; acc.w += ws * x.w;
    }
    float wd = g_inv_dst[w];
    acc.x *= wd; acc.y *= wd; acc.z *= wd; acc.w *= wd;
    reinterpret_cast<float4*>(m + (size_t)w * kD)[lane] = acc;
}

// ---------------- [rows,128] x [128,128] + bias, ReLU (f32x2) ----------------
// 64-row tile per block, 256 threads, 8 rows (4 pairs) x 4 cols per thread.
constexpr int kPad = 66;
constexpr int kGemmSmemBytes = (128 * 128 + 128 * kPad) * 4; // 99328

__global__ void __launch_bounds__(256, 2)
k_gemm128(const float* __restrict__ A, const float* __restrict__ W,
          const float* __restrict__ b, float* __restrict__ C, int rows) {
    extern __shared__ float sm[];
    float* Ws = sm;                   // [128][128]
    float* As = sm + 128 * 128;       // [128 k][kPad rows]
    int t = threadIdx.x;
    int row0 = blockIdx.x * 64;

    const float4* W4 = reinterpret_cast<const float4*>(W);
    float4* Ws4 = reinterpret_cast<float4*>(Ws);
    #pragma unroll
    for (int i = 0; i < 16; ++i) Ws4[t + i * 256] = W4[t + i * 256];

    #pragma unroll
    for (int ii = 0; ii < 8; ++ii) {
        int i = t + ii * 256;
        int r  = i >> 5;            // 0..63
        int kc = (i & 31) * 4;      // 0..124
        int gr = row0 + r;
        float4 v = make_float4(0.f, 0.f, 0.f, 0.f);
        if (gr < rows) v = reinterpret_cast<const float4*>(A + (size_t)gr * 128)[i & 31];
        As[(kc + 0) * kPad + r] = v.x;
        As[(kc + 1) * kPad + r] = v.y;
        As[(kc + 2) * kPad + r] = v.z;
        As[(kc + 3) * kPad + r] = v.w;
    }
    __syncthreads();

    int rg = t >> 5;            // warp id -> rows rg*8 .. rg*8+7
    int cg = (t & 31) * 4;      // cols

    unsigned long long acc2[4][4];
    #pragma unroll
    for (int p = 0; p < 4; ++p)
        #pragma unroll
        for (int j = 0; j < 4; ++j) acc2[p][j] = 0ull;

    #pragma unroll 8
    for (int k = 0; k < 128; ++k) {
        float4 w4 = *reinterpret_cast<const float4*>(&Ws[k * 128 + cg]);
        unsigned long long wp0 = pack2(w4.x, w4.x);
        unsigned long long wp1 = pack2(w4.y, w4.y);
        unsigned long long wp2 = pack2(w4.z, w4.z);
        unsigned long long wp3 = pack2(w4.w, w4.w);
        const float* arow = &As[k * kPad + rg * 8];
        #pragma unroll
        for (int p = 0; p < 4; ++p) {
            unsigned long long a =
                *reinterpret_cast<const unsigned long long*>(arow + 2 * p); // broadcast
            acc2[p][0] = ffma2(a, wp0, acc2[p][0]);
            acc2[p][1] = ffma2(a, wp1, acc2[p][1]);
            acc2[p][2] = ffma2(a, wp2, acc2[p][2]);
            acc2[p][3] = ffma2(a, wp3, acc2[p][3]);
        }
    }

    float4 bb = *reinterpret_cast<const float4*>(&b[cg]);
    #pragma unroll
    for (int p = 0; p < 4; ++p) {
        float lo0, hi0, lo1, hi1, lo2, hi2, lo3, hi3;
        unpack2(acc2[p][0], lo0, hi0);
        unpack2(acc2[p][1], lo1, hi1);
        unpack2(acc2[p][2], lo2, hi2);
        unpack2(acc2[p][3], lo3, hi3);
        int row = row0 + rg * 8 + 2 * p;
        if (row < rows) {
            float4 o;
            o.x = fmaxf(lo0 + bb.x, 0.f);
            o.y = fmaxf(lo1 + bb.y, 0.f);
            o.z = fmaxf(lo2 + bb.z, 0.f);
            o.w = fmaxf(lo3 + bb.w, 0.f);
            *reinterpret_cast<float4*>(C + (size_t)row * 128 + cg) = o;
        }
        if (row + 1 < rows) {
            float4 o;
            o.x = fmaxf(hi0 + bb.x, 0.f);
            o.y = fmaxf(hi1 + bb.y, 0.f);
            o.z = fmaxf(hi2 + bb.z, 0.f);
            o.w = fmaxf(hi3 + bb.w, 0.f);
            *reinterpret_cast<float4*>(C + (size_t)(row + 1) * 128 + cg) = o;
        }
    }
}

// ---------------- pooling ----------------
__global__ void k_zero_pool() {
    int i = blockIdx.x * blockDim.x + threadIdx.x;
    if (i < kG * kD) g_emb[i] = 0.f;
    if (i < kG) g_gcnt[i] = 0;
}

__global__ void k_pool(const float* __restrict__ h, const int* __restrict__ gids) {
    int w = (blockIdx.x * blockDim.x + threadIdx.x) >> 5;
    int lane = threadIdx.x & 31;
    if (w >= kN) return;
    int gid = gids[w];
    float4 x = reinterpret_cast<const float4*>(h + (size_t)w * kD)[lane];
    float* e = g_emb + (size_t)gid * kD + lane * 4;
    atomicAdd(e + 0, x.x);
    atomicAdd(e + 1, x.y);
    atomicAdd(e + 2, x.z);
    atomicAdd(e + 3, x.w);
    if (lane == 0) atomicAdd(&g_gcnt[gid], 1);
}

__global__ void k_pool_norm() {
    int i = blockIdx.x * blockDim.x + threadIdx.x;
    if (i >= kG * kD) return;
    int g = i >> 7;
    float c = (float)max(g_gcnt[g], 1);
    g_emb[i] = g_emb[i] / c;
}

// ---------------- MLP head ----------------
__global__ void k_mlp(const float* __restrict__ X, const float* __restrict__ W,
                      const float* __restrict__ b, float* __restrict__ Y,
                      int K, int M) {
    int idx = blockIdx.x * blockDim.x + threadIdx.x;
    int c = idx % M;
    int g0 = (idx / M) * 8;
    if (g0 >= kG) return;
    float acc[8];
    #pragma unroll
    for (int j = 0; j < 8; ++j) acc[j] = 0.f;
    for (int k = 0; k < K; ++k) {
        float w = W[(size_t)k * M + c];
        #pragma unroll
        for (int j = 0; j < 8; ++j)
            acc[j] += X[(size_t)(g0 + j) * K + k] * w;
    }
    float bias = b[c];
    #pragma unroll
    for (int j = 0; j < 8; ++j)
        Y[(size_t)(g0 + j) * M + c] = fmaxf(acc[j] + bias, 0.f);
}

__global__ void k_final(const float* __restrict__ X, const float* __restrict__ W,
                        const float* __restrict__ b, float* __restrict__ out) {
    int g = (blockIdx.x * blockDim.x + threadIdx.x) >> 5;
    int lane = threadIdx.x & 31;
    if (g >= kG) return;
    float s = 0.f;
    #pragma unroll
    for (int k = lane; k < 256; k += 32) s += X[(size_t)g * 256 + k] * W[k];
    #pragma unroll
    for (int off = 16; off; off >>= 1) s += __shfl_down_sync(0xffffffffu, s, off);
    if (lane == 0) out[g] = s + b[0];
}

// ---------------- launch ----------------
extern "C" void kernel_launch(void* const* d_in, const int* in_sizes, int n_in,
                              void* d_out, int out_size) {
    const float* feats = (const float*)d_in[0];
    const int*   src   = (const int*)d_in[1];
    const int*   dst   = (const int*)d_in[2];
    const int*   gids  = (const int*)d_in[3];
    const float* W0 = (const float*)d_in[4];  const float* b0 = (const float*)d_in[5];
    const float* W1 = (const float*)d_in[6];  const float* b1 = (const float*)d_in[7];
    const float* W2 = (const float*)d_in[8];  const float* b2 = (const float*)d_in[9];
    const float* Wm0 = (const float*)d_in[10]; const float* bm0 = (const float*)d_in[11];
    const float* Wm1 = (const float*)d_in[12]; const float* bm1 = (const float*)d_in[13];
    const float* Wm2 = (const float*)d_in[14]; const float* bm2 = (const float*)d_in[15];
    float* out = (float*)d_out;

    float *bufA, *bufB, *emb, *x1, *x2;
    cudaGetSymbolAddress((void**)&bufA, g_bufA);
    cudaGetSymbolAddress((void**)&bufB, g_bufB);
    cudaGetSymbolAddress((void**)&emb,  g_emb);
    cudaGetSymbolAddress((void**)&x1,   g_x1);
    cudaGetSymbolAddress((void**)&x2,   g_x2);

    cudaFuncSetAttribute(k_gemm128, cudaFuncAttributeMaxDynamicSharedMemorySize,
                         kGemmSmemBytes);

    const int T = 256;
    int nBlkN = (kN + T - 1) / T;           // 391
    int nBlkE = (kE + T - 1) / T;           // 6250
    int nBlkWarpN = (kN * 32 + T - 1) / T;  // 12500
    int nBlkGemm = (kN + 63) / 64;          // 1563
    int nBlkPoolZ = (kG * kD + T - 1) / T;  // 1024

    // degrees + normalization coefficients
    k_zero_deg<<<nBlkN, T>>>();
    k_degrees<<<nBlkE, T>>>(src, dst);
    k_inv<<<nBlkN, T>>>();

    // CSR-by-dst build
    k_scan1<<<kScanBlocks, 1024>>>();
    k_scan_tops<<<1, 1024>>>();
    k_scan_add<<<nBlkN, T>>>();
    k_scatter<<<nBlkE, T>>>(src, dst);

    // 3 GCN layers: gather -> GEMM(+bias,ReLU)
    k_gather<<<nBlkWarpN, T>>>(feats, bufB);
    k_gemm128<<<nBlkGemm, T, kGemmSmemBytes>>>(bufB, W0, b0, bufA, kN);

    k_gather<<<nBlkWarpN, T>>>(bufA, bufB);
    k_gemm128<<<nBlkGemm, T, kGemmSmemBytes>>>(bufB, W1, b1, bufA, kN);

    k_gather<<<nBlkWarpN, T>>>(bufA, bufB);
    k_gemm128<<<nBlkGemm, T, kGemmSmemBytes>>>(bufB, W2, b2, bufA, kN);

    // average pooling per graph
    k_zero_pool<<<nBlkPoolZ, T>>>();
    k_pool<<<nBlkWarpN, T>>>(bufA, gids);
    k_pool_norm<<<nBlkPoolZ, T>>>();

    // MLP head
    k_mlp<<<(kG / 8) * 512 / T, T>>>(emb, Wm0, bm0, x1, 128, 512);
    k_mlp<<<(kG / 8) * 256 / T, T>>>(x1, Wm1, bm1, x2, 512, 256);
    k_final<<<(kG * 32) / T, T>>>(x2, Wm2, bm2, out);
}

// round 5
// speedup vs baseline: 1.4153x; 1.1588x over previous
#include <cuda_runtime.h>
#include <cuda_bf16.h>
#include <cstdint>

constexpr int kN = 100000;
constexpr int kE = 1600000;
constexpr int kG = 2048;
constexpr int kD = 128;
constexpr int kScanBlocks = (kN + 1023) / 1024; // 98

// ---------------- scratch (no allocations allowed) ----------------
__device__ float g_bufA[kN * kD];            // 51.2 MB (layer output h, fp32)
__device__ unsigned short g_mhi[kN * kD];    // 25.6 MB (gathered m, bf16 hi)
__device__ unsigned short g_mlo[kN * kD];    // 25.6 MB (gathered m, bf16 lo)
__device__ unsigned short g_whi[3 * kD * kD]; // W bf16 hi, [K][N], per layer
__device__ unsigned short g_wlo[3 * kD * kD]; // W bf16 lo, [K][N], per layer
__device__ float g_inv_src[kN];
__device__ float g_inv_dst[kN];
__device__ int   g_deg_out[kN];
__device__ int   g_deg_in[kN];
__device__ int   g_row_ptr[kN + 1];
__device__ int   g_cursor[kN];
__device__ int   g_edge_src[kE];
__device__ int   g_blk[kScanBlocks];
__device__ float g_emb[kG * kD];
__device__ int   g_gcnt[kG];
__device__ float g_x1[kG * 512];
__device__ float g_x2[kG * 256];

// ---------------- bf16 helpers ----------------
__device__ __forceinline__ unsigned short f2bf(float x) {
    __nv_bfloat16 b = __float2bfloat16(x);
    return *reinterpret_cast<unsigned short*>(&b);
}
__device__ __forceinline__ float bf2f(unsigned short u) {
    __nv_bfloat16 b;
    *reinterpret_cast<unsigned short*>(&b) = u;
    return __bfloat162float(b);
}

// ---------------- mma / ldmatrix helpers (base ISA, sm_80+) ----------------
__device__ __forceinline__ uint32_t smem_u32(const void* p) {
    uint32_t a;
    asm("{ .reg .u64 t; cvta.to.shared.u64 t, %1; cvt.u32.u64 %0, t; }" : "=r"(a) : "l"(p));
    return a;
}
__device__ __forceinline__ void ldsm_x4(uint32_t* r, uint32_t addr) {
    asm volatile("ldmatrix.sync.aligned.m8n8.x4.shared.b16 {%0,%1,%2,%3}, [%4];"
                 : "=r"(r[0]), "=r"(r[1]), "=r"(r[2]), "=r"(r[3]) : "r"(addr));
}
__device__ __forceinline__ void ldsm_x4_t(uint32_t* r, uint32_t addr) {
    asm volatile("ldmatrix.sync.aligned.m8n8.x4.trans.shared.b16 {%0,%1,%2,%3}, [%4];"
                 : "=r"(r[0]), "=r"(r[1]), "=r"(r[2]), "=r"(r[3]) : "r"(addr));
}
__device__ __forceinline__ void mma16816(float* d, const uint32_t* a, const uint32_t* b) {
    asm volatile(
        "mma.sync.aligned.m16n8k16.row.col.f32.bf16.bf16.f32 "
        "{%0,%1,%2,%3}, {%4,%5,%6,%7}, {%8,%9}, {%0,%1,%2,%3};"
        : "+f"(d[0]), "+f"(d[1]), "+f"(d[2]), "+f"(d[3])
        : "r"(a[0]), "r"(a[1]), "r"(a[2]), "r"(a[3]), "r"(b[0]), "r"(b[1]));
}

// ---------------- setup kernels ----------------
__global__ void k_zero_deg() {
    int i = blockIdx.x * blockDim.x + threadIdx.x;
    if (i < kN) { g_deg_out[i] = 0; g_deg_in[i] = 0; }
}

__global__ void k_degrees(const int* __restrict__ src, const int* __restrict__ dst) {
    int e = blockIdx.x * blockDim.x + threadIdx.x;
    if (e >= kE) return;
    atomicAdd(&g_deg_out[src[e]], 1);
    atomicAdd(&g_deg_in[dst[e]], 1);
}

__global__ void k_inv() {
    int i = blockIdx.x * blockDim.x + threadIdx.x;
    if (i >= kN) return;
    g_inv_src[i] = rsqrtf((float)max(g_deg_out[i], 1));
    g_inv_dst[i] = rsqrtf((float)max(g_deg_in[i], 1));
}

__global__ void k_scan1() {
    __shared__ int sm[1024];
    int tid = threadIdx.x;
    int i = blockIdx.x * 1024 + tid;
    int v = (i < kN) ? g_deg_in[i] : 0;
    int x = v;
    sm[tid] = x;
    __syncthreads();
    for (int off = 1; off < 1024; off <<= 1) {
        int y = (tid >= off) ? sm[tid - off] : 0;
        __syncthreads();
        x += y;
        sm[tid] = x;
        __syncthreads();
    }
    if (i < kN) g_row_ptr[i] = x - v;
    if (tid == 1023) g_blk[blockIdx.x] = x;
}

__global__ void k_scan_tops() {
    __shared__ int sm[1024];
    int tid = threadIdx.x;
    int v = (tid < kScanBlocks) ? g_blk[tid] : 0;
    int x = v;
    sm[tid] = x;
    __syncthreads();
    for (int off = 1; off < 1024; off <<= 1) {
        int y = (tid >= off) ? sm[tid - off] : 0;
        __syncthreads();
        x += y;
        sm[tid] = x;
        __syncthreads();
    }
    if (tid < kScanBlocks) g_blk[tid] = x - v;
}

__global__ void k_scan_add() {
    int i = blockIdx.x * blockDim.x + threadIdx.x;
    if (i < kN) {
        int rp = g_row_ptr[i] + g_blk[i >> 10];
        g_row_ptr[i] = rp;
        g_cursor[i]  = rp;
    }
    if (i == 0) g_row_ptr[kN] = kE;
}

__global__ void k_scatter(const int* __restrict__ src, const int* __restrict__ dst) {
    int e = blockIdx.x * blockDim.x + threadIdx.x;
    if (e >= kE) return;
    int d = dst[e];
    int pos = atomicAdd(&g_cursor[d], 1);
    g_edge_src[pos] = src[e];
}

// W [K=128][N=128] fp32 row-major -> bf16 hi/lo, SAME layout (k-major, for mma B)
__global__ void k_wsplit(const float* __restrict__ W, unsigned short* __restrict__ whi,
                         unsigned short* __restrict__ wlo) {
    int i = blockIdx.x * blockDim.x + threadIdx.x;
    if (i >= kD * kD) return;
    float w = W[i];
    unsigned short h = f2bf(w);
    whi[i] = h;
    wlo[i] = f2bf(w - bf2f(h));
}

// ---------------- GCN aggregation: one warp per dst node -> bf16 hi/lo ----------------
__global__ void k_gather(const float* __restrict__ h) {
    int w = (blockIdx.x * blockDim.x + threadIdx.x) >> 5;
    int lane = threadIdx.x & 31;
    if (w >= kN) return;
    int e0 = g_row_ptr[w];
    int e1 = g_row_ptr[w + 1];
    const float4* H4 = reinterpret_cast<const float4*>(h);
    float4 acc = make_float4(0.f, 0.f, 0.f, 0.f);
    int e = e0;
    for (; e + 3 < e1; e += 4) {
        int s0 = g_edge_src[e + 0];
        int s1 = g_edge_src[e + 1];
        int s2 = g_edge_src[e + 2];
        int s3 = g_edge_src[e + 3];
        float4 x0 = H4[(size_t)s0 * 32 + lane];
        float4 x1 = H4[(size_t)s1 * 32 + lane];
        float4 x2 = H4[(size_t)s2 * 32 + lane];
        float4 x3 = H4[(size_t)s3 * 32 + lane];
        float w0 = g_inv_src[s0], w1 = g_inv_src[s1];
        float w2 = g_inv_src[s2], w3 = g_inv_src[s3];
        acc.x += w0 * x0.x + w1 * x1.x + w2 * x2.x + w3 * x3.x;
        acc.y += w0 * x0.y + w1 * x1.y + w2 * x2.y + w3 * x3.y;
        acc.z += w0 * x0.z + w1 * x1.z + w2 * x2.z + w3 * x3.z;
        acc.w += w0 * x0.w + w1 * x1.w + w2 * x2.w + w3 * x3.w;
    }
    for (; e < e1; ++e) {
        int s = g_edge_src[e];
        float ws = g_inv_src[s];
        float4 x = H4[(size_t)s * 32 + lane];
        acc.x += ws * x.x; acc.y += ws * x.y;
        acc.z += ws * x.z; acc.w += ws * x.w;
    }
    float wd = g_inv_dst[w];
    acc.x *= wd; acc.y *= wd; acc.z *= wd; acc.w *= wd;

    unsigned short h0 = f2bf(acc.x), h1 = f2bf(acc.y), h2 = f2bf(acc.z), h3 = f2bf(acc.w);
    unsigned short l0 = f2bf(acc.x - bf2f(h0));
    unsigned short l1 = f2bf(acc.y - bf2f(h1));
    unsigned short l2 = f2bf(acc.z - bf2f(h2));
    unsigned short l3 = f2bf(acc.w - bf2f(h3));
    unsigned long long hv = (unsigned long long)h0 | ((unsigned long long)h1 << 16) |
                            ((unsigned long long)h2 << 32) | ((unsigned long long)h3 << 48);
    unsigned long long lv = (unsigned long long)l0 | ((unsigned long long)l1 << 16) |
                            ((unsigned long long)l2 << 32) | ((unsigned long long)l3 << 48);
    *reinterpret_cast<unsigned long long*>(g_mhi + (size_t)w * kD + lane * 4) = hv;
    *reinterpret_cast<unsigned long long*>(g_mlo + (size_t)w * kD + lane * 4) = lv;
}

// ---------------- mma.sync GEMM: [128,128] tile, bf16x3, fp32 out ----------------
constexpr int kSA = 136;                         // padded row stride (bf16 elems)
constexpr int kTileB = 128 * kSA * 2;            // 34816 bytes per tile
constexpr int kOffAhi = 0;
constexpr int kOffAlo = kTileB;
constexpr int kOffBhi = 2 * kTileB;
constexpr int kOffBlo = 3 * kTileB;
constexpr int kMmaSmemBytes = 4 * kTileB;        // 139264

// stage a 128x128 bf16 tile (row-major src, 128 cols) into padded smem
__device__ __forceinline__ void stage_tile(char* smem, int off,
                                           const unsigned short* __restrict__ src,
                                           int row0, int rows, int tid) {
    #pragma unroll
    for (int it = 0; it < 8; ++it) {
        int chunk = tid + it * 256;        // 0..2047
        int r = chunk >> 4;                // 0..127
        int c8 = (chunk & 15) << 3;        // 0..120
        uint4 v = make_uint4(0u, 0u, 0u, 0u);
        int gr = row0 + r;
        if (gr < rows) v = *reinterpret_cast<const uint4*>(src + (size_t)gr * 128 + c8);
        *reinterpret_cast<uint4*>(smem + off + (r * kSA + c8) * 2) = v;
    }
}

__global__ void __launch_bounds__(256, 1)
k_gemm_mma(const unsigned short* __restrict__ Ahi, const unsigned short* __restrict__ Alo,
           const unsigned short* __restrict__ Bhi, const unsigned short* __restrict__ Blo,
           const float* __restrict__ bias, float* __restrict__ out, int rows) {
    extern __shared__ char smem[];
    uint32_t sb = smem_u32(smem);
    int tid = threadIdx.x;
    int lane = tid & 31;
    int wid = tid >> 5;
    int row0 = blockIdx.x * 128;

    stage_tile(smem, kOffAhi, Ahi, row0, rows, tid);
    stage_tile(smem, kOffAlo, Alo, row0, rows, tid);
    stage_tile(smem, kOffBhi, Bhi, 0, 128, tid);
    stage_tile(smem, kOffBlo, Blo, 0, 128, tid);
    __syncthreads();

    int wm = wid & 3;            // 4 m-warps: rows wm*32 .. +31
    int wn = wid >> 2;           // 2 n-warps: cols wn*64 .. +63
    int base_m = wm * 32;
    int base_n = wn * 64;

    // ldmatrix lane addressing (same shape for A and B):
    // row_in_16 = lane & 15, col8 = (lane >> 4) * 8
    int l16 = lane & 15;
    int c8  = (lane >> 4) << 3;
    // A: addr(mt, ks) = ((base_m + mt*16 + l16) * kSA + ks*16 + c8) * 2
    uint32_t a_base = sb + ((base_m + l16) * kSA + c8) * 2;
    // B: addr(np, ks) = ((ks*16 + l16) * kSA + base_n + np*16 + c8) * 2
    uint32_t b_base = sb + (l16 * kSA + base_n + c8) * 2;

    float acc[16][4];
    #pragma unroll
    for (int t = 0; t < 16; ++t)
        #pragma unroll
        for (int j = 0; j < 4; ++j) acc[t][j] = 0.f;

    #pragma unroll
    for (int pass = 0; pass < 3; ++pass) {
        int offA = (pass == 2) ? kOffAlo : kOffAhi;
        int offB = (pass == 1) ? kOffBlo : kOffBhi;
        #pragma unroll
        for (int ks = 0; ks < 8; ++ks) {
            uint32_t af[2][4];
            ldsm_x4(af[0], a_base + offA + 0 * 16 * kSA * 2 + ks * 32);
            ldsm_x4(af[1], a_base + offA + 1 * 16 * kSA * 2 + ks * 32);
            uint32_t bf[4][4];
            #pragma unroll
            for (int np = 0; np < 4; ++np)
                ldsm_x4_t(bf[np], b_base + offB + ks * 16 * kSA * 2 + np * 32);
            #pragma unroll
            for (int mt = 0; mt < 2; ++mt)
                #pragma unroll
                for (int nt = 0; nt < 8; ++nt)
                    mma16816(acc[mt * 8 + nt], af[mt], &bf[nt >> 1][(nt & 1) * 2]);
        }
    }

    // epilogue: bias + ReLU, fp32 out
    #pragma unroll
    for (int mt = 0; mt < 2; ++mt) {
        int r0 = row0 + base_m + mt * 16 + (lane >> 2);
        #pragma unroll
        for (int nt = 0; nt < 8; ++nt) {
            const float* a = acc[mt * 8 + nt];
            int col = base_n + nt * 8 + ((lane & 3) << 1);
            float2 bb = *reinterpret_cast<const float2*>(&bias[col]);
            if (r0 < rows) {
                float2 o;
                o.x = fmaxf(a[0] + bb.x, 0.f);
                o.y = fmaxf(a[1] + bb.y, 0.f);
                *reinterpret_cast<float2*>(out + (size_t)r0 * 128 + col) = o;
            }
            if (r0 + 8 < rows) {
                float2 o;
                o.x = fmaxf(a[2] + bb.x, 0.f);
                o.y = fmaxf(a[3] + bb.y, 0.f);
                *reinterpret_cast<float2*>(out + (size_t)(r0 + 8) * 128 + col) = o;
            }
        }
    }
}

// ---------------- pooling ----------------
__global__ void k_zero_pool() {
    int i = blockIdx.x * blockDim.x + threadIdx.x;
    if (i < kG * kD) g_emb[i] = 0.f;
    if (i < kG) g_gcnt[i] = 0;
}

__global__ void k_pool(const float* __restrict__ h, const int* __restrict__ gids) {
    int w = (blockIdx.x * blockDim.x + threadIdx.x) >> 5;
    int lane = threadIdx.x & 31;
    if (w >= kN) return;
    int gid = gids[w];
    float4 x = reinterpret_cast<const float4*>(h + (size_t)w * kD)[lane];
    float* e = g_emb + (size_t)gid * kD + lane * 4;
    atomicAdd(e + 0, x.x);
    atomicAdd(e + 1, x.y);
    atomicAdd(e + 2, x.z);
    atomicAdd(e + 3, x.w);
    if (lane == 0) atomicAdd(&g_gcnt[gid], 1);
}

__global__ void k_pool_norm() {
    int i = blockIdx.x * blockDim.x + threadIdx.x;
    if (i >= kG * kD) return;
    int g = i >> 7;
    float c = (float)max(g_gcnt[g], 1);
    g_emb[i] = g_emb[i] / c;
}

// ---------------- MLP head ----------------
__global__ void k_mlp(const float* __restrict__ X, const float* __restrict__ W,
                      const float* __restrict__ b, float* __restrict__ Y,
                      int K, int M) {
    int idx = blockIdx.x * blockDim.x + threadIdx.x;
    int c = idx % M;
    int g0 = (idx / M) * 8;
    if (g0 >= kG) return;
    float acc[8];
    #pragma unroll
    for (int j = 0; j < 8; ++j) acc[j] = 0.f;
    for (int k = 0; k < K; ++k) {
        float w = W[(size_t)k * M + c];
        #pragma unroll
        for (int j = 0; j < 8; ++j)
            acc[j] += X[(size_t)(g0 + j) * K + k] * w;
    }
    float bias = b[c];
    #pragma unroll
    for (int j = 0; j < 8; ++j)
        Y[(size_t)(g0 + j) * M + c] = fmaxf(acc[j] + bias, 0.f);
}

__global__ void k_final(const float* __restrict__ X, const float* __restrict__ W,
                        const float* __restrict__ b, float* __restrict__ out) {
    int g = (blockIdx.x * blockDim.x + threadIdx.x) >> 5;
    int lane = threadIdx.x & 31;
    if (g >= kG) return;
    float s = 0.f;
    #pragma unroll
    for (int k = lane; k < 256; k += 32) s += X[(size_t)g * 256 + k] * W[k];
    #pragma unroll
    for (int off = 16; off; off >>= 1) s += __shfl_down_sync(0xffffffffu, s, off);
    if (lane == 0) out[g] = s + b[0];
}

// ---------------- launch ----------------
extern "C" void kernel_launch(void* const* d_in, const int* in_sizes, int n_in,
                              void* d_out, int out_size) {
    const float* feats = (const float*)d_in[0];
    const int*   src   = (const int*)d_in[1];
    const int*   dst   = (const int*)d_in[2];
    const int*   gids  = (const int*)d_in[3];
    const float* W0 = (const float*)d_in[4];  const float* b0 = (const float*)d_in[5];
    const float* W1 = (const float*)d_in[6];  const float* b1 = (const float*)d_in[7];
    const float* W2 = (const float*)d_in[8];  const float* b2 = (const float*)d_in[9];
    const float* Wm0 = (const float*)d_in[10]; const float* bm0 = (const float*)d_in[11];
    const float* Wm1 = (const float*)d_in[12]; const float* bm1 = (const float*)d_in[13];
    const float* Wm2 = (const float*)d_in[14]; const float* bm2 = (const float*)d_in[15];
    float* out = (float*)d_out;

    float *bufA, *emb, *x1, *x2;
    unsigned short *mhi, *mlo, *whi, *wlo;
    cudaGetSymbolAddress((void**)&bufA, g_bufA);
    cudaGetSymbolAddress((void**)&emb,  g_emb);
    cudaGetSymbolAddress((void**)&x1,   g_x1);
    cudaGetSymbolAddress((void**)&x2,   g_x2);
    cudaGetSymbolAddress((void**)&mhi,  g_mhi);
    cudaGetSymbolAddress((void**)&mlo,  g_mlo);
    cudaGetSymbolAddress((void**)&whi,  g_whi);
    cudaGetSymbolAddress((void**)&wlo,  g_wlo);

    cudaFuncSetAttribute(k_gemm_mma, cudaFuncAttributeMaxDynamicSharedMemorySize,
                         kMmaSmemBytes);

    const int T = 256;
    int nBlkN = (kN + T - 1) / T;           // 391
    int nBlkE = (kE + T - 1) / T;           // 6250
    int nBlkWarpN = (kN * 32 + T - 1) / T;  // 12500
    int nBlkTc = (kN + 127) / 128;          // 782
    int nBlkPoolZ = (kG * kD + T - 1) / T;  // 1024
    int nBlkW = (kD * kD + T - 1) / T;      // 64

    // degrees + normalization coefficients
    k_zero_deg<<<nBlkN, T>>>();
    k_degrees<<<nBlkE, T>>>(src, dst);
    k_inv<<<nBlkN, T>>>();

    // CSR-by-dst build
    k_scan1<<<kScanBlocks, 1024>>>();
    k_scan_tops<<<1, 1024>>>();
    k_scan_add<<<nBlkN, T>>>();
    k_scatter<<<nBlkE, T>>>(src, dst);

    // weight split (bf16 hi/lo, k-major)
    k_wsplit<<<nBlkW, T>>>(W0, whi + 0 * kD * kD, wlo + 0 * kD * kD);
    k_wsplit<<<nBlkW, T>>>(W1, whi + 1 * kD * kD, wlo + 1 * kD * kD);
    k_wsplit<<<nBlkW, T>>>(W2, whi + 2 * kD * kD, wlo + 2 * kD * kD);

    // 3 GCN layers: gather(->bf16 hi/lo) -> mma.sync GEMM (+bias, ReLU, fp32)
    k_gather<<<nBlkWarpN, T>>>(feats);
    k_gemm_mma<<<nBlkTc, T, kMmaSmemBytes>>>(mhi, mlo, whi + 0 * kD * kD, wlo + 0 * kD * kD,
                                             b0, bufA, kN);
    k_gather<<<nBlkWarpN, T>>>(bufA);
    k_gemm_mma<<<nBlkTc, T, kMmaSmemBytes>>>(mhi, mlo, whi + 1 * kD * kD, wlo + 1 * kD * kD,
                                             b1, bufA, kN);
    k_gather<<<nBlkWarpN, T>>>(bufA);
    k_gemm_mma<<<nBlkTc, T, kMmaSmemBytes>>>(mhi, mlo, whi + 2 * kD * kD, wlo + 2 * kD * kD,
                                             b2, bufA, kN);

    // average pooling per graph
    k_zero_pool<<<nBlkPoolZ, T>>>();
    k_pool<<<nBlkWarpN, T>>>(bufA, gids);
    k_pool_norm<<<nBlkPoolZ, T>>>();

    // MLP head
    k_mlp<<<(kG / 8) * 512 / T, T>>>(emb, Wm0, bm0, x1, 128, 512);
    k_mlp<<<(kG / 8) * 256 / T, T>>>(x1, Wm1, bm1, x2, 512, 256);
    k_final<<<(kG * 32) / T, T>>>(x2, Wm2, bm2, out);
}

// round 6
// speedup vs baseline: 1.5452x; 1.0917x over previous
#include <cuda_runtime.h>
#include <cuda_bf16.h>
#include <cuda_fp16.h>
#include <cstdint>

constexpr int kN = 100000;
constexpr int kE = 1600000;
constexpr int kG = 2048;
constexpr int kD = 128;
constexpr int kScanBlocks = (kN + 1023) / 1024; // 98

// ---------------- scratch (no allocations allowed) ----------------
__device__ __half g_h16[kN * kD];            // 25.6 MB (gather input / layer output, fp16)
__device__ unsigned short g_mhi[kN * kD];    // 25.6 MB (gathered m, bf16 hi)
__device__ unsigned short g_mlo[kN * kD];    // 25.6 MB (gathered m, bf16 lo)
__device__ unsigned short g_whi[3 * kD * kD]; // W bf16 hi, [K][N], per layer
__device__ unsigned short g_wlo[3 * kD * kD]; // W bf16 lo, [K][N], per layer
__device__ float g_inv_src[kN];
__device__ float g_inv_dst[kN];
__device__ int   g_deg_out[kN];
__device__ int   g_deg_in[kN];
__device__ int   g_row_ptr[kN + 1];
__device__ int   g_cursor[kN];
__device__ int   g_edge_src[kE];
__device__ int   g_blk[kScanBlocks];
__device__ float g_emb[kG * kD];
__device__ int   g_gcnt[kG];
__device__ float g_x1[kG * 512];
__device__ float g_x2[kG * 256];

// ---------------- bf16 helpers ----------------
__device__ __forceinline__ unsigned short f2bf(float x) {
    __nv_bfloat16 b = __float2bfloat16(x);
    return *reinterpret_cast<unsigned short*>(&b);
}
__device__ __forceinline__ float bf2f(unsigned short u) {
    __nv_bfloat16 b;
    *reinterpret_cast<unsigned short*>(&b) = u;
    return __bfloat162float(b);
}

// ---------------- mma / ldmatrix helpers (base ISA, sm_80+) ----------------
__device__ __forceinline__ uint32_t smem_u32(const void* p) {
    uint32_t a;
    asm("{ .reg .u64 t; cvta.to.shared.u64 t, %1; cvt.u32.u64 %0, t; }" : "=r"(a) : "l"(p));
    return a;
}
__device__ __forceinline__ void ldsm_x4(uint32_t* r, uint32_t addr) {
    asm volatile("ldmatrix.sync.aligned.m8n8.x4.shared.b16 {%0,%1,%2,%3}, [%4];"
                 : "=r"(r[0]), "=r"(r[1]), "=r"(r[2]), "=r"(r[3]) : "r"(addr));
}
__device__ __forceinline__ void ldsm_x4_t(uint32_t* r, uint32_t addr) {
    asm volatile("ldmatrix.sync.aligned.m8n8.x4.trans.shared.b16 {%0,%1,%2,%3}, [%4];"
                 : "=r"(r[0]), "=r"(r[1]), "=r"(r[2]), "=r"(r[3]) : "r"(addr));
}
__device__ __forceinline__ void mma16816(float* d, const uint32_t* a, const uint32_t* b) {
    asm volatile(
        "mma.sync.aligned.m16n8k16.row.col.f32.bf16.bf16.f32 "
        "{%0,%1,%2,%3}, {%4,%5,%6,%7}, {%8,%9}, {%0,%1,%2,%3};"
        : "+f"(d[0]), "+f"(d[1]), "+f"(d[2]), "+f"(d[3])
        : "r"(a[0]), "r"(a[1]), "r"(a[2]), "r"(a[3]), "r"(b[0]), "r"(b[1]));
}

// ---------------- setup kernels ----------------
// zeroes degrees, emb, gcnt (all re-inited every launch)
__global__ void k_zero_deg() {
    int i = blockIdx.x * blockDim.x + threadIdx.x;
    if (i < kN) { g_deg_out[i] = 0; g_deg_in[i] = 0; }
    if (i < kG * kD) g_emb[i] = 0.f;
    if (i < kG) g_gcnt[i] = 0;
}

__global__ void k_degrees(const int* __restrict__ src, const int* __restrict__ dst) {
    int e = blockIdx.x * blockDim.x + threadIdx.x;
    if (e >= kE) return;
    atomicAdd(&g_deg_out[src[e]], 1);
    atomicAdd(&g_deg_in[dst[e]], 1);
}

// inv norms + per-graph node counts
__global__ void k_inv(const int* __restrict__ gids) {
    int i = blockIdx.x * blockDim.x + threadIdx.x;
    if (i >= kN) return;
    g_inv_src[i] = rsqrtf((float)max(g_deg_out[i], 1));
    g_inv_dst[i] = rsqrtf((float)max(g_deg_in[i], 1));
    atomicAdd(&g_gcnt[gids[i]], 1);
}

__global__ void k_scan1() {
    __shared__ int sm[1024];
    int tid = threadIdx.x;
    int i = blockIdx.x * 1024 + tid;
    int v = (i < kN) ? g_deg_in[i] : 0;
    int x = v;
    sm[tid] = x;
    __syncthreads();
    for (int off = 1; off < 1024; off <<= 1) {
        int y = (tid >= off) ? sm[tid - off] : 0;
        __syncthreads();
        x += y;
        sm[tid] = x;
        __syncthreads();
    }
    if (i < kN) g_row_ptr[i] = x - v;
    if (tid == 1023) g_blk[blockIdx.x] = x;
}

__global__ void k_scan_tops() {
    __shared__ int sm[1024];
    int tid = threadIdx.x;
    int v = (tid < kScanBlocks) ? g_blk[tid] : 0;
    int x = v;
    sm[tid] = x;
    __syncthreads();
    for (int off = 1; off < 1024; off <<= 1) {
        int y = (tid >= off) ? sm[tid - off] : 0;
        __syncthreads();
        x += y;
        sm[tid] = x;
        __syncthreads();
    }
    if (tid < kScanBlocks) g_blk[tid] = x - v;
}

__global__ void k_scan_add() {
    int i = blockIdx.x * blockDim.x + threadIdx.x;
    if (i < kN) {
        int rp = g_row_ptr[i] + g_blk[i >> 10];
        g_row_ptr[i] = rp;
        g_cursor[i]  = rp;
    }
    if (i == 0) g_row_ptr[kN] = kE;
}

__global__ void k_scatter(const int* __restrict__ src, const int* __restrict__ dst) {
    int e = blockIdx.x * blockDim.x + threadIdx.x;
    if (e >= kE) return;
    int d = dst[e];
    int pos = atomicAdd(&g_cursor[d], 1);
    g_edge_src[pos] = src[e];
}

// W [K=128][N=128] fp32 row-major -> bf16 hi/lo, SAME layout (k-major, for mma B)
__global__ void k_wsplit(const float* __restrict__ W, unsigned short* __restrict__ whi,
                         unsigned short* __restrict__ wlo) {
    int i = blockIdx.x * blockDim.x + threadIdx.x;
    if (i >= kD * kD) return;
    float w = W[i];
    unsigned short h = f2bf(w);
    whi[i] = h;
    wlo[i] = f2bf(w - bf2f(h));
}

// feats fp32 -> fp16
__global__ void k_f2h(const float* __restrict__ x, __half* __restrict__ y) {
    int i = blockIdx.x * blockDim.x + threadIdx.x;
    if (i >= kN * kD / 4) return;
    float4 v = reinterpret_cast<const float4*>(x)[i];
    __half2 a = __floats2half2_rn(v.x, v.y);
    __half2 b = __floats2half2_rn(v.z, v.w);
    reinterpret_cast<__half2*>(y)[2 * i + 0] = a;
    reinterpret_cast<__half2*>(y)[2 * i + 1] = b;
}

// ---------------- GCN aggregation: one warp per dst node, fp16 in -> bf16 hi/lo ----------------
__global__ void k_gather(const __half* __restrict__ h) {
    int w = (blockIdx.x * blockDim.x + threadIdx.x) >> 5;
    int lane = threadIdx.x & 31;
    if (w >= kN) return;
    int e0 = g_row_ptr[w];
    int e1 = g_row_ptr[w + 1];
    const uint2* H2 = reinterpret_cast<const uint2*>(h);  // 8B = 4 halfs per lane
    float4 acc = make_float4(0.f, 0.f, 0.f, 0.f);
    int e = e0;
    for (; e + 3 < e1; e += 4) {
        int s0 = g_edge_src[e + 0];
        int s1 = g_edge_src[e + 1];
        int s2 = g_edge_src[e + 2];
        int s3 = g_edge_src[e + 3];
        uint2 r0 = H2[(size_t)s0 * 32 + lane];
        uint2 r1 = H2[(size_t)s1 * 32 + lane];
        uint2 r2 = H2[(size_t)s2 * 32 + lane];
        uint2 r3 = H2[(size_t)s3 * 32 + lane];
        float w0 = g_inv_src[s0], w1 = g_inv_src[s1];
        float w2 = g_inv_src[s2], w3 = g_inv_src[s3];
        float2 a0 = __half22float2(*reinterpret_cast<__half2*>(&r0.x));
        float2 b0 = __half22float2(*reinterpret_cast<__half2*>(&r0.y));
        float2 a1 = __half22float2(*reinterpret_cast<__half2*>(&r1.x));
        float2 b1 = __half22float2(*reinterpret_cast<__half2*>(&r1.y));
        float2 a2 = __half22float2(*reinterpret_cast<__half2*>(&r2.x));
        float2 b2 = __half22float2(*reinterpret_cast<__half2*>(&r2.y));
        float2 a3 = __half22float2(*reinterpret_cast<__half2*>(&r3.x));
        float2 b3 = __half22float2(*reinterpret_cast<__half2*>(&r3.y));
        acc.x += w0 * a0.x + w1 * a1.x + w2 * a2.x + w3 * a3.x;
        acc.y += w0 * a0.y + w1 * a1.y + w2 * a2.y + w3 * a3.y;
        acc.z += w0 * b0.x + w1 * b1.x + w2 * b2.x + w3 * b3.x;
        acc.w += w0 * b0.y + w1 * b1.y + w2 * b2.y + w3 * b3.y;
    }
    for (; e < e1; ++e) {
        int s = g_edge_src[e];
        float ws = g_inv_src[s];
        uint2 r = H2[(size_t)s * 32 + lane];
        float2 a = __half22float2(*reinterpret_cast<__half2*>(&r.x));
        float2 b = __half22float2(*reinterpret_cast<__half2*>(&r.y));
        acc.x += ws * a.x; acc.y += ws * a.y;
        acc.z += ws * b.x; acc.w += ws * b.y;
    }
    float wd = g_inv_dst[w];
    acc.x *= wd; acc.y *= wd; acc.z *= wd; acc.w *= wd;

    unsigned short h0 = f2bf(acc.x), h1 = f2bf(acc.y), h2 = f2bf(acc.z), h3 = f2bf(acc.w);
    unsigned short l0 = f2bf(acc.x - bf2f(h0));
    unsigned short l1 = f2bf(acc.y - bf2f(h1));
    unsigned short l2 = f2bf(acc.z - bf2f(h2));
    unsigned short l3 = f2bf(acc.w - bf2f(h3));
    unsigned long long hv = (unsigned long long)h0 | ((unsigned long long)h1 << 16) |
                            ((unsigned long long)h2 << 32) | ((unsigned long long)h3 << 48);
    unsigned long long lv = (unsigned long long)l0 | ((unsigned long long)l1 << 16) |
                            ((unsigned long long)l2 << 32) | ((unsigned long long)l3 << 48);
    *reinterpret_cast<unsigned long long*>(g_mhi + (size_t)w * kD + lane * 4) = hv;
    *reinterpret_cast<unsigned long long*>(g_mlo + (size_t)w * kD + lane * 4) = lv;
}

// ---------------- mma.sync GEMM: [128,128] tile, bf16x3, fused epilogues ----------------
constexpr int kSA = 136;                         // padded row stride (bf16 elems)
constexpr int kTileB = 128 * kSA * 2;            // 34816 bytes per tile
constexpr int kOffAhi = 0;
constexpr int kOffAlo = kTileB;
constexpr int kOffBhi = 2 * kTileB;
constexpr int kOffBlo = 3 * kTileB;
constexpr int kMmaSmemBytes = 4 * kTileB;        // 139264

__device__ __forceinline__ void stage_tile(char* smem, int off,
                                           const unsigned short* __restrict__ src,
                                           int row0, int rows, int tid) {
    #pragma unroll
    for (int it = 0; it < 8; ++it) {
        int chunk = tid + it * 256;        // 0..2047
        int r = chunk >> 4;                // 0..127
        int c8 = (chunk & 15) << 3;        // 0..120
        uint4 v = make_uint4(0u, 0u, 0u, 0u);
        int gr = row0 + r;
        if (gr < rows) v = *reinterpret_cast<const uint4*>(src + (size_t)gr * 128 + c8);
        *reinterpret_cast<uint4*>(smem + off + (r * kSA + c8) * 2) = v;
    }
}

// EPI = 0: write fp16 h; EPI = 1: atomicAdd into g_emb (avg-pool, counts applied later)
template <int EPI>
__global__ void __launch_bounds__(256, 1)
k_gemm_mma(const unsigned short* __restrict__ Ahi, const unsigned short* __restrict__ Alo,
           const unsigned short* __restrict__ Bhi, const unsigned short* __restrict__ Blo,
           const float* __restrict__ bias, __half* __restrict__ outH,
           const int* __restrict__ gids, float* __restrict__ emb, int rows) {
    extern __shared__ char smem[];
    uint32_t sb = smem_u32(smem);
    int tid = threadIdx.x;
    int lane = tid & 31;
    int wid = tid >> 5;
    int row0 = blockIdx.x * 128;

    stage_tile(smem, kOffAhi, Ahi, row0, rows, tid);
    stage_tile(smem, kOffAlo, Alo, row0, rows, tid);
    stage_tile(smem, kOffBhi, Bhi, 0, 128, tid);
    stage_tile(smem, kOffBlo, Blo, 0, 128, tid);
    __syncthreads();

    int wm = wid & 3;            // 4 m-warps: rows wm*32 .. +31
    int wn = wid >> 2;           // 2 n-warps: cols wn*64 .. +63
    int base_m = wm * 32;
    int base_n = wn * 64;

    int l16 = lane & 15;
    int c8  = (lane >> 4) << 3;
    uint32_t a_base = sb + ((base_m + l16) * kSA + c8) * 2;
    uint32_t b_base = sb + (l16 * kSA + base_n + c8) * 2;

    float acc[16][4];
    #pragma unroll
    for (int t = 0; t < 16; ++t)
        #pragma unroll
        for (int j = 0; j < 4; ++j) acc[t][j] = 0.f;

    #pragma unroll
    for (int pass = 0; pass < 3; ++pass) {
        int offA = (pass == 2) ? kOffAlo : kOffAhi;
        int offB = (pass == 1) ? kOffBlo : kOffBhi;
        #pragma unroll
        for (int ks = 0; ks < 8; ++ks) {
            uint32_t af[2][4];
            ldsm_x4(af[0], a_base + offA + 0 * 16 * kSA * 2 + ks * 32);
            ldsm_x4(af[1], a_base + offA + 1 * 16 * kSA * 2 + ks * 32);
            uint32_t bf[4][4];
            #pragma unroll
            for (int np = 0; np < 4; ++np)
                ldsm_x4_t(bf[np], b_base + offB + ks * 16 * kSA * 2 + np * 32);
            #pragma unroll
            for (int mt = 0; mt < 2; ++mt)
                #pragma unroll
                for (int nt = 0; nt < 8; ++nt)
                    mma16816(acc[mt * 8 + nt], af[mt], &bf[nt >> 1][(nt & 1) * 2]);
        }
    }

    #pragma unroll
    for (int mt = 0; mt < 2; ++mt) {
        int r0 = row0 + base_m + mt * 16 + (lane >> 2);
        int r1 = r0 + 8;
        int gid0 = -1, gid1 = -1;
        if (EPI == 1) {
            if (r0 < rows) gid0 = gids[r0];
            if (r1 < rows) gid1 = gids[r1];
        }
        #pragma unroll
        for (int nt = 0; nt < 8; ++nt) {
            const float* a = acc[mt * 8 + nt];
            int col = base_n + nt * 8 + ((lane & 3) << 1);
            float2 bb = *reinterpret_cast<const float2*>(&bias[col]);
            float o0x = fmaxf(a[0] + bb.x, 0.f);
            float o0y = fmaxf(a[1] + bb.y, 0.f);
            float o1x = fmaxf(a[2] + bb.x, 0.f);
            float o1y = fmaxf(a[3] + bb.y, 0.f);
            if (EPI == 0) {
                if (r0 < rows)
                    *reinterpret_cast<__half2*>(outH + (size_t)r0 * 128 + col) =
                        __floats2half2_rn(o0x, o0y);
                if (r1 < rows)
                    *reinterpret_cast<__half2*>(outH + (size_t)r1 * 128 + col) =
                        __floats2half2_rn(o1x, o1y);
            } else {
                if (gid0 >= 0) {
                    atomicAdd(emb + (size_t)gid0 * 128 + col,     o0x);
                    atomicAdd(emb + (size_t)gid0 * 128 + col + 1, o0y);
                }
                if (gid1 >= 0) {
                    atomicAdd(emb + (size_t)gid1 * 128 + col,     o1x);
                    atomicAdd(emb + (size_t)gid1 * 128 + col + 1, o1y);
                }
            }
        }
    }
}

// ---------------- pool normalization ----------------
__global__ void k_pool_norm() {
    int i = blockIdx.x * blockDim.x + threadIdx.x;
    if (i >= kG * kD) return;
    int g = i >> 7;
    float c = (float)max(g_gcnt[g], 1);
    g_emb[i] = g_emb[i] / c;
}

// ---------------- MLP head ----------------
__global__ void k_mlp(const float* __restrict__ X, const float* __restrict__ W,
                      const float* __restrict__ b, float* __restrict__ Y,
                      int K, int M) {
    int idx = blockIdx.x * blockDim.x + threadIdx.x;
    int c = idx % M;
    int g0 = (idx / M) * 8;
    if (g0 >= kG) return;
    float acc[8];
    #pragma unroll
    for (int j = 0; j < 8; ++j) acc[j] = 0.f;
    for (int k = 0; k < K; ++k) {
        float w = W[(size_t)k * M + c];
        #pragma unroll
        for (int j = 0; j < 8; ++j)
            acc[j] += X[(size_t)(g0 + j) * K + k] * w;
    }
    float bias = b[c];
    #pragma unroll
    for (int j = 0; j < 8; ++j)
        Y[(size_t)(g0 + j) * M + c] = fmaxf(acc[j] + bias, 0.f);
}

__global__ void k_final(const float* __restrict__ X, const float* __restrict__ W,
                        const float* __restrict__ b, float* __restrict__ out) {
    int g = (blockIdx.x * blockDim.x + threadIdx.x) >> 5;
    int lane = threadIdx.x & 31;
    if (g >= kG) return;
    float s = 0.f;
    #pragma unroll
    for (int k = lane; k < 256; k += 32) s += X[(size_t)g * 256 + k] * W[k];
    #pragma unroll
    for (int off = 16; off; off >>= 1) s += __shfl_down_sync(0xffffffffu, s, off);
    if (lane == 0) out[g] = s + b[0];
}

// ---------------- launch ----------------
extern "C" void kernel_launch(void* const* d_in, const int* in_sizes, int n_in,
                              void* d_out, int out_size) {
    const float* feats = (const float*)d_in[0];
    const int*   src   = (const int*)d_in[1];
    const int*   dst   = (const int*)d_in[2];
    const int*   gids  = (const int*)d_in[3];
    const float* W0 = (const float*)d_in[4];  const float* b0 = (const float*)d_in[5];
    const float* W1 = (const float*)d_in[6];  const float* b1 = (const float*)d_in[7];
    const float* W2 = (const float*)d_in[8];  const float* b2 = (const float*)d_in[9];
    const float* Wm0 = (const float*)d_in[10]; const float* bm0 = (const float*)d_in[11];
    const float* Wm1 = (const float*)d_in[12]; const float* bm1 = (const float*)d_in[13];
    const float* Wm2 = (const float*)d_in[14]; const float* bm2 = (const float*)d_in[15];
    float* out = (float*)d_out;

    float *emb, *x1, *x2;
    __half* h16;
    unsigned short *mhi, *mlo, *whi, *wlo;
    cudaGetSymbolAddress((void**)&emb,  g_emb);
    cudaGetSymbolAddress((void**)&x1,   g_x1);
    cudaGetSymbolAddress((void**)&x2,   g_x2);
    cudaGetSymbolAddress((void**)&h16,  g_h16);
    cudaGetSymbolAddress((void**)&mhi,  g_mhi);
    cudaGetSymbolAddress((void**)&mlo,  g_mlo);
    cudaGetSymbolAddress((void**)&whi,  g_whi);
    cudaGetSymbolAddress((void**)&wlo,  g_wlo);

    cudaFuncSetAttribute(k_gemm_mma<0>, cudaFuncAttributeMaxDynamicSharedMemorySize,
                         kMmaSmemBytes);
    cudaFuncSetAttribute(k_gemm_mma<1>, cudaFuncAttributeMaxDynamicSharedMemorySize,
                         kMmaSmemBytes);

    const int T = 256;
    int nBlkN = (kN + T - 1) / T;           // 391
    int nBlkZ = (kG * kD + T - 1) / T;      // 1024 (covers kN and kG*kD)
    int nBlkE = (kE + T - 1) / T;           // 6250
    int nBlkWarpN = (kN * 32 + T - 1) / T;  // 12500
    int nBlkTc = (kN + 127) / 128;          // 782
    int nBlkW = (kD * kD + T - 1) / T;      // 64
    int nBlkH = (kN * kD / 4 + T - 1) / T;  // 12500

    // degrees + norms + graph counts + zero pool
    k_zero_deg<<<nBlkZ, T>>>();
    k_degrees<<<nBlkE, T>>>(src, dst);
    k_inv<<<nBlkN, T>>>(gids);

    // CSR-by-dst build
    k_scan1<<<kScanBlocks, 1024>>>();
    k_scan_tops<<<1, 1024>>>();
    k_scan_add<<<nBlkN, T>>>();
    k_scatter<<<nBlkE, T>>>(src, dst);

    // weight split (bf16 hi/lo, k-major) + feats fp16
    k_wsplit<<<nBlkW, T>>>(W0, whi + 0 * kD * kD, wlo + 0 * kD * kD);
    k_wsplit<<<nBlkW, T>>>(W1, whi + 1 * kD * kD, wlo + 1 * kD * kD);
    k_wsplit<<<nBlkW, T>>>(W2, whi + 2 * kD * kD, wlo + 2 * kD * kD);
    k_f2h<<<nBlkH, T>>>(feats, h16);

    // 3 GCN layers: gather(fp16 -> bf16 hi/lo) -> mma GEMM (+bias, ReLU)
    k_gather<<<nBlkWarpN, T>>>(h16);
    k_gemm_mma<0><<<nBlkTc, T, kMmaSmemBytes>>>(mhi, mlo, whi + 0 * kD * kD,
                                                wlo + 0 * kD * kD, b0, h16, gids, emb, kN);
    k_gather<<<nBlkWarpN, T>>>(h16);
    k_gemm_mma<0><<<nBlkTc, T, kMmaSmemBytes>>>(mhi, mlo, whi + 1 * kD * kD,
                                                wlo + 1 * kD * kD, b1, h16, gids, emb, kN);
    k_gather<<<nBlkWarpN, T>>>(h16);
    k_gemm_mma<1><<<nBlkTc, T, kMmaSmemBytes>>>(mhi, mlo, whi + 2 * kD * kD,
                                                wlo + 2 * kD * kD, b2, h16, gids, emb, kN);

    // pool normalize
    k_pool_norm<<<nBlkZ, T>>>();

    // MLP head
    k_mlp<<<(kG / 8) * 512 / T, T>>>(emb, Wm0, bm0, x1, 128, 512);
    k_mlp<<<(kG / 8) * 256 / T, T>>>(x1, Wm1, bm1, x2, 512, 256);
    k_final<<<(kG * 32) / T, T>>>(x2, Wm2, bm2, out);
}

// round 7
// speedup vs baseline: 1.6742x; 1.0835x over previous
#include <cuda_runtime.h>
#include <cuda_bf16.h>
#include <cuda_fp16.h>
#include <cstdint>

constexpr int kN = 100000;
constexpr int kE = 1600000;
constexpr int kG = 2048;
constexpr int kD = 128;
constexpr int kScanBlocks = (kN + 1023) / 1024; // 98

// ---------------- scratch (no allocations allowed) ----------------
__device__ __half g_h16[kN * kD];            // 25.6 MB (pre-scaled rows, fp16)
__device__ unsigned short g_mhi[kN * kD];    // 25.6 MB (gathered m, bf16 hi)
__device__ unsigned short g_mlo[kN * kD];    // 25.6 MB (gathered m, bf16 lo)
__device__ unsigned short g_whi[3 * kD * kD]; // W bf16 hi, [K][N], per layer
__device__ unsigned short g_wlo[3 * kD * kD]; // W bf16 lo, [K][N], per layer
__device__ float g_inv_src[kN];
__device__ float g_inv_dst[kN];
__device__ int   g_deg_out[kN];
__device__ int   g_deg_in[kN];
__device__ int   g_row_ptr[kN + 1];
__device__ int   g_cursor[kN];
__device__ int   g_edge_src[kE];
__device__ int   g_blk[kScanBlocks];
__device__ float g_emb[kG * kD];
__device__ int   g_gcnt[kG];
__device__ float g_x1[kG * 512];
__device__ float g_x2[kG * 256];

// ---------------- bf16 helpers ----------------
__device__ __forceinline__ unsigned short f2bf(float x) {
    __nv_bfloat16 b = __float2bfloat16(x);
    return *reinterpret_cast<unsigned short*>(&b);
}
__device__ __forceinline__ float bf2f(unsigned short u) {
    __nv_bfloat16 b;
    *reinterpret_cast<unsigned short*>(&b) = u;
    return __bfloat162float(b);
}

// ---------------- mma / ldmatrix helpers (base ISA, sm_80+) ----------------
__device__ __forceinline__ uint32_t smem_u32(const void* p) {
    uint32_t a;
    asm("{ .reg .u64 t; cvta.to.shared.u64 t, %1; cvt.u32.u64 %0, t; }" : "=r"(a) : "l"(p));
    return a;
}
__device__ __forceinline__ void ldsm_x4(uint32_t* r, uint32_t addr) {
    asm volatile("ldmatrix.sync.aligned.m8n8.x4.shared.b16 {%0,%1,%2,%3}, [%4];"
                 : "=r"(r[0]), "=r"(r[1]), "=r"(r[2]), "=r"(r[3]) : "r"(addr));
}
__device__ __forceinline__ void ldsm_x4_t(uint32_t* r, uint32_t addr) {
    asm volatile("ldmatrix.sync.aligned.m8n8.x4.trans.shared.b16 {%0,%1,%2,%3}, [%4];"
                 : "=r"(r[0]), "=r"(r[1]), "=r"(r[2]), "=r"(r[3]) : "r"(addr));
}
__device__ __forceinline__ void mma16816(float* d, const uint32_t* a, const uint32_t* b) {
    asm volatile(
        "mma.sync.aligned.m16n8k16.row.col.f32.bf16.bf16.f32 "
        "{%0,%1,%2,%3}, {%4,%5,%6,%7}, {%8,%9}, {%0,%1,%2,%3};"
        : "+f"(d[0]), "+f"(d[1]), "+f"(d[2]), "+f"(d[3])
        : "r"(a[0]), "r"(a[1]), "r"(a[2]), "r"(a[3]), "r"(b[0]), "r"(b[1]));
}

// ---------------- setup kernels ----------------
__global__ void k_zero() {
    int i = blockIdx.x * blockDim.x + threadIdx.x;
    if (i < kN) { g_deg_out[i] = 0; g_deg_in[i] = 0; }
    if (i < kG * kD) g_emb[i] = 0.f;
    if (i < kG) g_gcnt[i] = 0;
}

__global__ void k_degrees(const int* __restrict__ src, const int* __restrict__ dst) {
    int e = blockIdx.x * blockDim.x + threadIdx.x;
    if (e >= kE) return;
    atomicAdd(&g_deg_out[src[e]], 1);
    atomicAdd(&g_deg_in[dst[e]], 1);
}

__global__ void k_scan1() {
    __shared__ int sm[1024];
    int tid = threadIdx.x;
    int i = blockIdx.x * 1024 + tid;
    int v = (i < kN) ? g_deg_in[i] : 0;
    int x = v;
    sm[tid] = x;
    __syncthreads();
    for (int off = 1; off < 1024; off <<= 1) {
        int y = (tid >= off) ? sm[tid - off] : 0;
        __syncthreads();
        x += y;
        sm[tid] = x;
        __syncthreads();
    }
    if (i < kN) g_row_ptr[i] = x - v;
    if (tid == 1023) g_blk[blockIdx.x] = x;
}

__global__ void k_scan_tops() {
    __shared__ int sm[1024];
    int tid = threadIdx.x;
    int v = (tid < kScanBlocks) ? g_blk[tid] : 0;
    int x = v;
    sm[tid] = x;
    __syncthreads();
    for (int off = 1; off < 1024; off <<= 1) {
        int y = (tid >= off) ? sm[tid - off] : 0;
        __syncthreads();
        x += y;
        sm[tid] = x;
        __syncthreads();
    }
    if (tid < kScanBlocks) g_blk[tid] = x - v;
}

// scan finalize + inv norms + per-graph counts (merged)
__global__ void k_scan_add_inv(const int* __restrict__ gids) {
    int i = blockIdx.x * blockDim.x + threadIdx.x;
    if (i < kN) {
        int rp = g_row_ptr[i] + g_blk[i >> 10];
        g_row_ptr[i] = rp;
        g_cursor[i]  = rp;
        g_inv_src[i] = rsqrtf((float)max(g_deg_out[i], 1));
        g_inv_dst[i] = rsqrtf((float)max(g_deg_in[i], 1));
        atomicAdd(&g_gcnt[gids[i]], 1);
    }
    if (i == 0) g_row_ptr[kN] = kE;
}

__global__ void k_scatter(const int* __restrict__ src, const int* __restrict__ dst) {
    int e = blockIdx.x * blockDim.x + threadIdx.x;
    if (e >= kE) return;
    int d = dst[e];
    int pos = atomicAdd(&g_cursor[d], 1);
    g_edge_src[pos] = src[e];
}

// all 3 weight splits in one launch: W [K][N] fp32 -> bf16 hi/lo same layout
__global__ void k_wsplit_all(const float* __restrict__ W0, const float* __restrict__ W1,
                             const float* __restrict__ W2) {
    int layer = blockIdx.x >> 6;            // 64 blocks per layer
    int i = (blockIdx.x & 63) * 256 + threadIdx.x;
    if (i >= kD * kD) return;
    const float* W = (layer == 0) ? W0 : (layer == 1) ? W1 : W2;
    float w = W[i];
    unsigned short h = f2bf(w);
    g_whi[layer * kD * kD + i] = h;
    g_wlo[layer * kD * kD + i] = f2bf(w - bf2f(h));
}

// feats fp32 -> fp16, PRE-SCALED by inv_src[row]
__global__ void k_f2h(const float* __restrict__ x) {
    int i = blockIdx.x * blockDim.x + threadIdx.x;
    if (i >= kN * kD / 4) return;
    int row = i >> 5;                        // 32 float4 per row
    float s = g_inv_src[row];
    float4 v = reinterpret_cast<const float4*>(x)[i];
    __half2 a = __floats2half2_rn(v.x * s, v.y * s);
    __half2 b = __floats2half2_rn(v.z * s, v.w * s);
    reinterpret_cast<__half2*>(g_h16)[2 * i + 0] = a;
    reinterpret_cast<__half2*>(g_h16)[2 * i + 1] = b;
}

// ---------------- GCN aggregation: one warp per dst node ----------------
// rows are pre-scaled by inv_src, so inner loop = pure sum of rows
__global__ void k_gather() {
    int w = (blockIdx.x * blockDim.x + threadIdx.x) >> 5;
    int lane = threadIdx.x & 31;
    if (w >= kN) return;
    int e0 = g_row_ptr[w];
    int e1 = g_row_ptr[w + 1];
    const uint2* H2 = reinterpret_cast<const uint2*>(g_h16);
    float4 acc = make_float4(0.f, 0.f, 0.f, 0.f);
    int e = e0;
    for (; e + 7 < e1; e += 8) {
        int s0 = g_edge_src[e + 0];
        int s1 = g_edge_src[e + 1];
        int s2 = g_edge_src[e + 2];
        int s3 = g_edge_src[e + 3];
        int s4 = g_edge_src[e + 4];
        int s5 = g_edge_src[e + 5];
        int s6 = g_edge_src[e + 6];
        int s7 = g_edge_src[e + 7];
        uint2 r0 = H2[(size_t)s0 * 32 + lane];
        uint2 r1 = H2[(size_t)s1 * 32 + lane];
        uint2 r2 = H2[(size_t)s2 * 32 + lane];
        uint2 r3 = H2[(size_t)s3 * 32 + lane];
        uint2 r4 = H2[(size_t)s4 * 32 + lane];
        uint2 r5 = H2[(size_t)s5 * 32 + lane];
        uint2 r6 = H2[(size_t)s6 * 32 + lane];
        uint2 r7 = H2[(size_t)s7 * 32 + lane];
        #define ACC(r) { \
            float2 a_ = __half22float2(*reinterpret_cast<__half2*>(&(r).x)); \
            float2 b_ = __half22float2(*reinterpret_cast<__half2*>(&(r).y)); \
            acc.x += a_.x; acc.y += a_.y; acc.z += b_.x; acc.w += b_.y; }
        ACC(r0) ACC(r1) ACC(r2) ACC(r3) ACC(r4) ACC(r5) ACC(r6) ACC(r7)
    }
    for (; e < e1; ++e) {
        int s = g_edge_src[e];
        uint2 r = H2[(size_t)s * 32 + lane];
        ACC(r)
    }
    #undef ACC
    float wd = g_inv_dst[w];
    acc.x *= wd; acc.y *= wd; acc.z *= wd; acc.w *= wd;

    unsigned short h0 = f2bf(acc.x), h1 = f2bf(acc.y), h2 = f2bf(acc.z), h3 = f2bf(acc.w);
    unsigned short l0 = f2bf(acc.x - bf2f(h0));
    unsigned short l1 = f2bf(acc.y - bf2f(h1));
    unsigned short l2 = f2bf(acc.z - bf2f(h2));
    unsigned short l3 = f2bf(acc.w - bf2f(h3));
    unsigned long long hv = (unsigned long long)h0 | ((unsigned long long)h1 << 16) |
                            ((unsigned long long)h2 << 32) | ((unsigned long long)h3 << 48);
    unsigned long long lv = (unsigned long long)l0 | ((unsigned long long)l1 << 16) |
                            ((unsigned long long)l2 << 32) | ((unsigned long long)l3 << 48);
    *reinterpret_cast<unsigned long long*>(g_mhi + (size_t)w * kD + lane * 4) = hv;
    *reinterpret_cast<unsigned long long*>(g_mlo + (size_t)w * kD + lane * 4) = lv;
}

// ---------------- mma.sync GEMM: [128,128] tile, bf16x3, fused epilogues ----------------
constexpr int kSA = 136;
constexpr int kTileB = 128 * kSA * 2;
constexpr int kOffAhi = 0;
constexpr int kOffAlo = kTileB;
constexpr int kOffBhi = 2 * kTileB;
constexpr int kOffBlo = 3 * kTileB;
constexpr int kMmaSmemBytes = 4 * kTileB;        // 139264

__device__ __forceinline__ void stage_tile(char* smem, int off,
                                           const unsigned short* __restrict__ src,
                                           int row0, int rows, int tid) {
    #pragma unroll
    for (int it = 0; it < 8; ++it) {
        int chunk = tid + it * 256;
        int r = chunk >> 4;
        int c8 = (chunk & 15) << 3;
        uint4 v = make_uint4(0u, 0u, 0u, 0u);
        int gr = row0 + r;
        if (gr < rows) v = *reinterpret_cast<const uint4*>(src + (size_t)gr * 128 + c8);
        *reinterpret_cast<uint4*>(smem + off + (r * kSA + c8) * 2) = v;
    }
}

// EPI=0: write fp16 h PRE-SCALED by inv_src[row]; EPI=1: atomicAdd into g_emb
template <int EPI>
__global__ void __launch_bounds__(256, 1)
k_gemm_mma(const unsigned short* __restrict__ Bhi, const unsigned short* __restrict__ Blo,
           const float* __restrict__ bias, const int* __restrict__ gids, int rows) {
    extern __shared__ char smem[];
    uint32_t sb = smem_u32(smem);
    int tid = threadIdx.x;
    int lane = tid & 31;
    int wid = tid >> 5;
    int row0 = blockIdx.x * 128;

    stage_tile(smem, kOffAhi, g_mhi, row0, rows, tid);
    stage_tile(smem, kOffAlo, g_mlo, row0, rows, tid);
    stage_tile(smem, kOffBhi, Bhi, 0, 128, tid);
    stage_tile(smem, kOffBlo, Blo, 0, 128, tid);
    __syncthreads();

    int wm = wid & 3;
    int wn = wid >> 2;
    int base_m = wm * 32;
    int base_n = wn * 64;

    int l16 = lane & 15;
    int c8  = (lane >> 4) << 3;
    uint32_t a_base = sb + ((base_m + l16) * kSA + c8) * 2;
    uint32_t b_base = sb + (l16 * kSA + base_n + c8) * 2;

    float acc[16][4];
    #pragma unroll
    for (int t = 0; t < 16; ++t)
        #pragma unroll
        for (int j = 0; j < 4; ++j) acc[t][j] = 0.f;

    #pragma unroll
    for (int pass = 0; pass < 3; ++pass) {
        int offA = (pass == 2) ? kOffAlo : kOffAhi;
        int offB = (pass == 1) ? kOffBlo : kOffBhi;
        #pragma unroll
        for (int ks = 0; ks < 8; ++ks) {
            uint32_t af[2][4];
            ldsm_x4(af[0], a_base + offA + 0 * 16 * kSA * 2 + ks * 32);
            ldsm_x4(af[1], a_base + offA + 1 * 16 * kSA * 2 + ks * 32);
            uint32_t bf[4][4];
            #pragma unroll
            for (int np = 0; np < 4; ++np)
                ldsm_x4_t(bf[np], b_base + offB + ks * 16 * kSA * 2 + np * 32);
            #pragma unroll
            for (int mt = 0; mt < 2; ++mt)
                #pragma unroll
                for (int nt = 0; nt < 8; ++nt)
                    mma16816(acc[mt * 8 + nt], af[mt], &bf[nt >> 1][(nt & 1) * 2]);
        }
    }

    #pragma unroll
    for (int mt = 0; mt < 2; ++mt) {
        int r0 = row0 + base_m + mt * 16 + (lane >> 2);
        int r1 = r0 + 8;
        int gid0 = -1, gid1 = -1;
        float sc0 = 0.f, sc1 = 0.f;
        if (EPI == 1) {
            if (r0 < rows) gid0 = gids[r0];
            if (r1 < rows) gid1 = gids[r1];
        } else {
            if (r0 < rows) sc0 = g_inv_src[r0];
            if (r1 < rows) sc1 = g_inv_src[r1];
        }
        #pragma unroll
        for (int nt = 0; nt < 8; ++nt) {
            const float* a = acc[mt * 8 + nt];
            int col = base_n + nt * 8 + ((lane & 3) << 1);
            float2 bb = *reinterpret_cast<const float2*>(&bias[col]);
            float o0x = fmaxf(a[0] + bb.x, 0.f);
            float o0y = fmaxf(a[1] + bb.y, 0.f);
            float o1x = fmaxf(a[2] + bb.x, 0.f);
            float o1y = fmaxf(a[3] + bb.y, 0.f);
            if (EPI == 0) {
                if (r0 < rows)
                    *reinterpret_cast<__half2*>(g_h16 + (size_t)r0 * 128 + col) =
                        __floats2half2_rn(o0x * sc0, o0y * sc0);
                if (r1 < rows)
                    *reinterpret_cast<__half2*>(g_h16 + (size_t)r1 * 128 + col) =
                        __floats2half2_rn(o1x * sc1, o1y * sc1);
            } else {
                if (gid0 >= 0) {
                    atomicAdd(g_emb + (size_t)gid0 * 128 + col,     o0x);
                    atomicAdd(g_emb + (size_t)gid0 * 128 + col + 1, o0y);
                }
                if (gid1 >= 0) {
                    atomicAdd(g_emb + (size_t)gid1 * 128 + col,     o1x);
                    atomicAdd(g_emb + (size_t)gid1 * 128 + col + 1, o1y);
                }
            }
        }
    }
}

// ---------------- MLP head (NORM: divide X rows by graph counts) ----------------
template <bool NORM>
__global__ void k_mlp(const float* __restrict__ X, const float* __restrict__ W,
                      const float* __restrict__ b, float* __restrict__ Y,
                      int K, int M) {
    int idx = blockIdx.x * blockDim.x + threadIdx.x;
    int c = idx % M;
    int g0 = (idx / M) * 8;
    if (g0 >= kG) return;
    float acc[8];
    #pragma unroll
    for (int j = 0; j < 8; ++j) acc[j] = 0.f;
    for (int k = 0; k < K; ++k) {
        float w = W[(size_t)k * M + c];
        #pragma unroll
        for (int j = 0; j < 8; ++j)
            acc[j] += X[(size_t)(g0 + j) * K + k] * w;
    }
    float bias = b[c];
    #pragma unroll
    for (int j = 0; j < 8; ++j) {
        float v = acc[j];
        if (NORM) v *= 1.f / (float)max(g_gcnt[g0 + j], 1);
        Y[(size_t)(g0 + j) * M + c] = fmaxf(v + bias, 0.f);
    }
}

__global__ void k_final(const float* __restrict__ X, const float* __restrict__ W,
                        const float* __restrict__ b, float* __restrict__ out) {
    int g = (blockIdx.x * blockDim.x + threadIdx.x) >> 5;
    int lane = threadIdx.x & 31;
    if (g >= kG) return;
    float s = 0.f;
    #pragma unroll
    for (int k = lane; k < 256; k += 32) s += X[(size_t)g * 256 + k] * W[k];
    #pragma unroll
    for (int off = 16; off; off >>= 1) s += __shfl_down_sync(0xffffffffu, s, off);
    if (lane == 0) out[g] = s + b[0];
}

// ---------------- launch ----------------
extern "C" void kernel_launch(void* const* d_in, const int* in_sizes, int n_in,
                              void* d_out, int out_size) {
    const float* feats = (const float*)d_in[0];
    const int*   src   = (const int*)d_in[1];
    const int*   dst   = (const int*)d_in[2];
    const int*   gids  = (const int*)d_in[3];
    const float* W0 = (const float*)d_in[4];  const float* b0 = (const float*)d_in[5];
    const float* W1 = (const float*)d_in[6];  const float* b1 = (const float*)d_in[7];
    const float* W2 = (const float*)d_in[8];  const float* b2 = (const float*)d_in[9];
    const float* Wm0 = (const float*)d_in[10]; const float* bm0 = (const float*)d_in[11];
    const float* Wm1 = (const float*)d_in[12]; const float* bm1 = (const float*)d_in[13];
    const float* Wm2 = (const float*)d_in[14]; const float* bm2 = (const float*)d_in[15];
    float* out = (float*)d_out;

    float *emb, *x1, *x2;
    unsigned short *whi, *wlo;
    cudaGetSymbolAddress((void**)&emb,  g_emb);
    cudaGetSymbolAddress((void**)&x1,   g_x1);
    cudaGetSymbolAddress((void**)&x2,   g_x2);
    cudaGetSymbolAddress((void**)&whi,  g_whi);
    cudaGetSymbolAddress((void**)&wlo,  g_wlo);

    cudaFuncSetAttribute(k_gemm_mma<0>, cudaFuncAttributeMaxDynamicSharedMemorySize,
                         kMmaSmemBytes);
    cudaFuncSetAttribute(k_gemm_mma<1>, cudaFuncAttributeMaxDynamicSharedMemorySize,
                         kMmaSmemBytes);

    const int T = 256;
    int nBlkN = (kN + T - 1) / T;           // 391
    int nBlkZ = (kG * kD + T - 1) / T;      // 1024
    int nBlkE = (kE + T - 1) / T;           // 6250
    int nBlkWarpN = (kN * 32 + T - 1) / T;  // 12500
    int nBlkTc = (kN + 127) / 128;          // 782
    int nBlkH = (kN * kD / 4 + T - 1) / T;  // 12500

    k_zero<<<nBlkZ, T>>>();
    k_degrees<<<nBlkE, T>>>(src, dst);
    k_scan1<<<kScanBlocks, 1024>>>();
    k_scan_tops<<<1, 1024>>>();
    k_scan_add_inv<<<nBlkN, T>>>(gids);
    k_scatter<<<nBlkE, T>>>(src, dst);
    k_wsplit_all<<<192, T>>>(W0, W1, W2);
    k_f2h<<<nBlkH, T>>>(feats);

    k_gather<<<nBlkWarpN, T>>>();
    k_gemm_mma<0><<<nBlkTc, T, kMmaSmemBytes>>>(whi + 0 * kD * kD, wlo + 0 * kD * kD,
                                                b0, gids, kN);
    k_gather<<<nBlkWarpN, T>>>();
    k_gemm_mma<0><<<nBlkTc, T, kMmaSmemBytes>>>(whi + 1 * kD * kD, wlo + 1 * kD * kD,
                                                b1, gids, kN);
    k_gather<<<nBlkWarpN, T>>>();
    k_gemm_mma<1><<<nBlkTc, T, kMmaSmemBytes>>>(whi + 2 * kD * kD, wlo + 2 * kD * kD,
                                                b2, gids, kN);

    k_mlp<true><<<(kG / 8) * 512 / T, T>>>(emb, Wm0, bm0, x1, 128, 512);
    k_mlp<false><<<(kG / 8) * 256 / T, T>>>(x1, Wm1, bm1, x2, 512, 256);
    k_final<<<(kG * 32) / T, T>>>(x2, Wm2, bm2, out);
}

// round 8
// speedup vs baseline: 1.8480x; 1.1038x over previous
#include <cuda_runtime.h>
#include <cuda_bf16.h>
#include <cuda_fp16.h>
#include <cstdint>

constexpr int kN = 100000;
constexpr int kE = 1600000;
constexpr int kG = 2048;
constexpr int kD = 128;
constexpr int kScanBlocks = (kN + 1023) / 1024; // 98

// ---------------- scratch (no allocations allowed) ----------------
__device__ __half g_h16[kN * kD];            // 25.6 MB (pre-scaled rows h, fp16)
__device__ __half g_m16[kN * kD];            // 25.6 MB (gathered m, fp16)
__device__ __half g_whi[3 * kD * kD];        // W fp16 hi, [K][N], per layer
__device__ __half g_wlo[3 * kD * kD];        // W fp16 lo, [K][N], per layer
__device__ float g_inv_src[kN];
__device__ float g_inv_dst[kN];
__device__ int   g_deg_out[kN];
__device__ int   g_deg_in[kN];
__device__ int   g_row_ptr[kN + 1];
__device__ int   g_cursor[kN];
__device__ int   g_edge_src[kE];
__device__ int   g_blk[kScanBlocks];
__device__ float g_emb[kG * kD];
__device__ int   g_gcnt[kG];
__device__ float g_x1[kG * 512];
__device__ float g_x2[kG * 256];

// ---------------- mma / ldmatrix helpers (base ISA, sm_80+) ----------------
__device__ __forceinline__ uint32_t smem_u32(const void* p) {
    uint32_t a;
    asm("{ .reg .u64 t; cvta.to.shared.u64 t, %1; cvt.u32.u64 %0, t; }" : "=r"(a) : "l"(p));
    return a;
}
__device__ __forceinline__ void ldsm_x4(uint32_t* r, uint32_t addr) {
    asm volatile("ldmatrix.sync.aligned.m8n8.x4.shared.b16 {%0,%1,%2,%3}, [%4];"
                 : "=r"(r[0]), "=r"(r[1]), "=r"(r[2]), "=r"(r[3]) : "r"(addr));
}
__device__ __forceinline__ void ldsm_x4_t(uint32_t* r, uint32_t addr) {
    asm volatile("ldmatrix.sync.aligned.m8n8.x4.trans.shared.b16 {%0,%1,%2,%3}, [%4];"
                 : "=r"(r[0]), "=r"(r[1]), "=r"(r[2]), "=r"(r[3]) : "r"(addr));
}
__device__ __forceinline__ void mma16816h(float* d, const uint32_t* a, const uint32_t* b) {
    asm volatile(
        "mma.sync.aligned.m16n8k16.row.col.f32.f16.f16.f32 "
        "{%0,%1,%2,%3}, {%4,%5,%6,%7}, {%8,%9}, {%0,%1,%2,%3};"
        : "+f"(d[0]), "+f"(d[1]), "+f"(d[2]), "+f"(d[3])
        : "r"(a[0]), "r"(a[1]), "r"(a[2]), "r"(a[3]), "r"(b[0]), "r"(b[1]));
}

// ---------------- setup kernels ----------------
__global__ void k_zero() {
    int i = blockIdx.x * blockDim.x + threadIdx.x;
    if (i < kN) { g_deg_out[i] = 0; g_deg_in[i] = 0; }
    if (i < kG * kD) g_emb[i] = 0.f;
    if (i < kG) g_gcnt[i] = 0;
}

__global__ void k_degrees(const int* __restrict__ src, const int* __restrict__ dst) {
    int e = blockIdx.x * blockDim.x + threadIdx.x;
    if (e >= kE) return;
    atomicAdd(&g_deg_out[src[e]], 1);
    atomicAdd(&g_deg_in[dst[e]], 1);
}

__global__ void k_scan1() {
    __shared__ int sm[1024];
    int tid = threadIdx.x;
    int i = blockIdx.x * 1024 + tid;
    int v = (i < kN) ? g_deg_in[i] : 0;
    int x = v;
    sm[tid] = x;
    __syncthreads();
    for (int off = 1; off < 1024; off <<= 1) {
        int y = (tid >= off) ? sm[tid - off] : 0;
        __syncthreads();
        x += y;
        sm[tid] = x;
        __syncthreads();
    }
    if (i < kN) g_row_ptr[i] = x - v;
    if (tid == 1023) g_blk[blockIdx.x] = x;
}

__global__ void k_scan_tops() {
    __shared__ int sm[1024];
    int tid = threadIdx.x;
    int v = (tid < kScanBlocks) ? g_blk[tid] : 0;
    int x = v;
    sm[tid] = x;
    __syncthreads();
    for (int off = 1; off < 1024; off <<= 1) {
        int y = (tid >= off) ? sm[tid - off] : 0;
        __syncthreads();
        x += y;
        sm[tid] = x;
        __syncthreads();
    }
    if (tid < kScanBlocks) g_blk[tid] = x - v;
}

__global__ void k_scan_add_inv(const int* __restrict__ gids) {
    int i = blockIdx.x * blockDim.x + threadIdx.x;
    if (i < kN) {
        int rp = g_row_ptr[i] + g_blk[i >> 10];
        g_row_ptr[i] = rp;
        g_cursor[i]  = rp;
        g_inv_src[i] = rsqrtf((float)max(g_deg_out[i], 1));
        g_inv_dst[i] = rsqrtf((float)max(g_deg_in[i], 1));
        atomicAdd(&g_gcnt[gids[i]], 1);
    }
    if (i == 0) g_row_ptr[kN] = kE;
}

__global__ void k_scatter(const int* __restrict__ src, const int* __restrict__ dst) {
    int e = blockIdx.x * blockDim.x + threadIdx.x;
    if (e >= kE) return;
    int d = dst[e];
    int pos = atomicAdd(&g_cursor[d], 1);
    g_edge_src[pos] = src[e];
}

// all 3 weight splits in one launch: W [K][N] fp32 -> fp16 hi/lo same layout
__global__ void k_wsplit_all(const float* __restrict__ W0, const float* __restrict__ W1,
                             const float* __restrict__ W2) {
    int layer = blockIdx.x >> 6;
    int i = (blockIdx.x & 63) * 256 + threadIdx.x;
    if (i >= kD * kD) return;
    const float* W = (layer == 0) ? W0 : (layer == 1) ? W1 : W2;
    float w = W[i];
    __half h = __float2half_rn(w);
    g_whi[layer * kD * kD + i] = h;
    g_wlo[layer * kD * kD + i] = __float2half_rn(w - __half2float(h));
}

// feats fp32 -> fp16, PRE-SCALED by inv_src[row]
__global__ void k_f2h(const float* __restrict__ x) {
    int i = blockIdx.x * blockDim.x + threadIdx.x;
    if (i >= kN * kD / 4) return;
    int row = i >> 5;
    float s = g_inv_src[row];
    float4 v = reinterpret_cast<const float4*>(x)[i];
    __half2 a = __floats2half2_rn(v.x * s, v.y * s);
    __half2 b = __floats2half2_rn(v.z * s, v.w * s);
    reinterpret_cast<__half2*>(g_h16)[2 * i + 0] = a;
    reinterpret_cast<__half2*>(g_h16)[2 * i + 1] = b;
}

// ---------------- GCN aggregation: one warp per dst node -> fp16 m ----------------
__global__ void k_gather() {
    int w = (blockIdx.x * blockDim.x + threadIdx.x) >> 5;
    int lane = threadIdx.x & 31;
    if (w >= kN) return;
    int e0 = g_row_ptr[w];
    int e1 = g_row_ptr[w + 1];
    const uint2* H2 = reinterpret_cast<const uint2*>(g_h16);
    float4 acc = make_float4(0.f, 0.f, 0.f, 0.f);
    int e = e0;
    for (; e + 7 < e1; e += 8) {
        int s0 = g_edge_src[e + 0];
        int s1 = g_edge_src[e + 1];
        int s2 = g_edge_src[e + 2];
        int s3 = g_edge_src[e + 3];
        int s4 = g_edge_src[e + 4];
        int s5 = g_edge_src[e + 5];
        int s6 = g_edge_src[e + 6];
        int s7 = g_edge_src[e + 7];
        uint2 r0 = H2[(size_t)s0 * 32 + lane];
        uint2 r1 = H2[(size_t)s1 * 32 + lane];
        uint2 r2 = H2[(size_t)s2 * 32 + lane];
        uint2 r3 = H2[(size_t)s3 * 32 + lane];
        uint2 r4 = H2[(size_t)s4 * 32 + lane];
        uint2 r5 = H2[(size_t)s5 * 32 + lane];
        uint2 r6 = H2[(size_t)s6 * 32 + lane];
        uint2 r7 = H2[(size_t)s7 * 32 + lane];
        #define ACC(r) { \
            float2 a_ = __half22float2(*reinterpret_cast<__half2*>(&(r).x)); \
            float2 b_ = __half22float2(*reinterpret_cast<__half2*>(&(r).y)); \
            acc.x += a_.x; acc.y += a_.y; acc.z += b_.x; acc.w += b_.y; }
        ACC(r0) ACC(r1) ACC(r2) ACC(r3) ACC(r4) ACC(r5) ACC(r6) ACC(r7)
    }
    for (; e < e1; ++e) {
        int s = g_edge_src[e];
        uint2 r = H2[(size_t)s * 32 + lane];
        ACC(r)
    }
    #undef ACC
    float wd = g_inv_dst[w];
    uint2 o;
    *reinterpret_cast<__half2*>(&o.x) = __floats2half2_rn(acc.x * wd, acc.y * wd);
    *reinterpret_cast<__half2*>(&o.y) = __floats2half2_rn(acc.z * wd, acc.w * wd);
    reinterpret_cast<uint2*>(g_m16)[(size_t)w * 32 + lane] = o;
}

// ---------------- mma.sync GEMM: [128,128] tile, fp16 A x (fp16 hi+lo W), fp32 acc ----------------
constexpr int kSA = 136;
constexpr int kTileB = 128 * kSA * 2;            // 34816 bytes
constexpr int kOffA   = 0;
constexpr int kOffBhi = kTileB;
constexpr int kOffBlo = 2 * kTileB;
constexpr int kMmaSmemBytes = 3 * kTileB;        // 104448 -> 2 CTAs/SM

__device__ __forceinline__ void stage_tile(char* smem, int off,
                                           const unsigned short* __restrict__ src,
                                           int row0, int rows, int tid) {
    #pragma unroll
    for (int it = 0; it < 8; ++it) {
        int chunk = tid + it * 256;
        int r = chunk >> 4;
        int c8 = (chunk & 15) << 3;
        uint4 v = make_uint4(0u, 0u, 0u, 0u);
        int gr = row0 + r;
        if (gr < rows) v = *reinterpret_cast<const uint4*>(src + (size_t)gr * 128 + c8);
        *reinterpret_cast<uint4*>(smem + off + (r * kSA + c8) * 2) = v;
    }
}

// EPI=0: write fp16 h PRE-SCALED by inv_src[row]; EPI=1: atomicAdd into g_emb
template <int EPI>
__global__ void __launch_bounds__(256, 2)
k_gemm_mma(const __half* __restrict__ Bhi, const __half* __restrict__ Blo,
           const float* __restrict__ bias, const int* __restrict__ gids, int rows) {
    extern __shared__ char smem[];
    uint32_t sb = smem_u32(smem);
    int tid = threadIdx.x;
    int lane = tid & 31;
    int wid = tid >> 5;
    int row0 = blockIdx.x * 128;

    stage_tile(smem, kOffA, reinterpret_cast<const unsigned short*>(g_m16), row0, rows, tid);
    stage_tile(smem, kOffBhi, reinterpret_cast<const unsigned short*>(Bhi), 0, 128, tid);
    stage_tile(smem, kOffBlo, reinterpret_cast<const unsigned short*>(Blo), 0, 128, tid);
    __syncthreads();

    int wm = wid & 3;
    int wn = wid >> 2;
    int base_m = wm * 32;
    int base_n = wn * 64;

    int l16 = lane & 15;
    int c8  = (lane >> 4) << 3;
    uint32_t a_base = sb + ((base_m + l16) * kSA + c8) * 2;
    uint32_t b_base = sb + (l16 * kSA + base_n + c8) * 2;

    float acc[16][4];
    #pragma unroll
    for (int t = 0; t < 16; ++t)
        #pragma unroll
        for (int j = 0; j < 4; ++j) acc[t][j] = 0.f;

    #pragma unroll
    for (int pass = 0; pass < 2; ++pass) {
        int offB = (pass == 0) ? kOffBhi : kOffBlo;
        #pragma unroll
        for (int ks = 0; ks < 8; ++ks) {
            uint32_t af[2][4];
            ldsm_x4(af[0], a_base + kOffA + 0 * 16 * kSA * 2 + ks * 32);
            ldsm_x4(af[1], a_base + kOffA + 1 * 16 * kSA * 2 + ks * 32);
            uint32_t bf[4][4];
            #pragma unroll
            for (int np = 0; np < 4; ++np)
                ldsm_x4_t(bf[np], b_base + offB + ks * 16 * kSA * 2 + np * 32);
            #pragma unroll
            for (int mt = 0; mt < 2; ++mt)
                #pragma unroll
                for (int nt = 0; nt < 8; ++nt)
                    mma16816h(acc[mt * 8 + nt], af[mt], &bf[nt >> 1][(nt & 1) * 2]);
        }
    }

    #pragma unroll
    for (int mt = 0; mt < 2; ++mt) {
        int r0 = row0 + base_m + mt * 16 + (lane >> 2);
        int r1 = r0 + 8;
        int gid0 = -1, gid1 = -1;
        float sc0 = 0.f, sc1 = 0.f;
        if (EPI == 1) {
            if (r0 < rows) gid0 = gids[r0];
            if (r1 < rows) gid1 = gids[r1];
        } else {
            if (r0 < rows) sc0 = g_inv_src[r0];
            if (r1 < rows) sc1 = g_inv_src[r1];
        }
        #pragma unroll
        for (int nt = 0; nt < 8; ++nt) {
            const float* a = acc[mt * 8 + nt];
            int col = base_n + nt * 8 + ((lane & 3) << 1);
            float2 bb = *reinterpret_cast<const float2*>(&bias[col]);
            float o0x = fmaxf(a[0] + bb.x, 0.f);
            float o0y = fmaxf(a[1] + bb.y, 0.f);
            float o1x = fmaxf(a[2] + bb.x, 0.f);
            float o1y = fmaxf(a[3] + bb.y, 0.f);
            if (EPI == 0) {
                if (r0 < rows)
                    *reinterpret_cast<__half2*>(g_h16 + (size_t)r0 * 128 + col) =
                        __floats2half2_rn(o0x * sc0, o0y * sc0);
                if (r1 < rows)
                    *reinterpret_cast<__half2*>(g_h16 + (size_t)r1 * 128 + col) =
                        __floats2half2_rn(o1x * sc1, o1y * sc1);
            } else {
                if (gid0 >= 0) {
                    atomicAdd(g_emb + (size_t)gid0 * 128 + col,     o0x);
                    atomicAdd(g_emb + (size_t)gid0 * 128 + col + 1, o0y);
                }
                if (gid1 >= 0) {
                    atomicAdd(g_emb + (size_t)gid1 * 128 + col,     o1x);
                    atomicAdd(g_emb + (size_t)gid1 * 128 + col + 1, o1y);
                }
            }
        }
    }
}

// ---------------- MLP head (NORM: divide X rows by graph counts) ----------------
template <bool NORM>
__global__ void k_mlp(const float* __restrict__ X, const float* __restrict__ W,
                      const float* __restrict__ b, float* __restrict__ Y,
                      int K, int M) {
    int idx = blockIdx.x * blockDim.x + threadIdx.x;
    int c = idx % M;
    int g0 = (idx / M) * 8;
    if (g0 >= kG) return;
    float acc[8];
    #pragma unroll
    for (int j = 0; j < 8; ++j) acc[j] = 0.f;
    for (int k = 0; k < K; ++k) {
        float w = W[(size_t)k * M + c];
        #pragma unroll
        for (int j = 0; j < 8; ++j)
            acc[j] += X[(size_t)(g0 + j) * K + k] * w;
    }
    float bias = b[c];
    #pragma unroll
    for (int j = 0; j < 8; ++j) {
        float v = acc[j];
        if (NORM) v *= 1.f / (float)max(g_gcnt[g0 + j], 1);
        Y[(size_t)(g0 + j) * M + c] = fmaxf(v + bias, 0.f);
    }
}

__global__ void k_final(const float* __restrict__ X, const float* __restrict__ W,
                        const float* __restrict__ b, float* __restrict__ out) {
    int g = (blockIdx.x * blockDim.x + threadIdx.x) >> 5;
    int lane = threadIdx.x & 31;
    if (g >= kG) return;
    float s = 0.f;
    #pragma unroll
    for (int k = lane; k < 256; k += 32) s += X[(size_t)g * 256 + k] * W[k];
    #pragma unroll
    for (int off = 16; off; off >>= 1) s += __shfl_down_sync(0xffffffffu, s, off);
    if (lane == 0) out[g] = s + b[0];
}

// ---------------- launch ----------------
extern "C" void kernel_launch(void* const* d_in, const int* in_sizes, int n_in,
                              void* d_out, int out_size) {
    const float* feats = (const float*)d_in[0];
    const int*   src   = (const int*)d_in[1];
    const int*   dst   = (const int*)d_in[2];
    const int*   gids  = (const int*)d_in[3];
    const float* W0 = (const float*)d_in[4];  const float* b0 = (const float*)d_in[5];
    const float* W1 = (const float*)d_in[6];  const float* b1 = (const float*)d_in[7];
    const float* W2 = (const float*)d_in[8];  const float* b2 = (const float*)d_in[9];
    const float* Wm0 = (const float*)d_in[10]; const float* bm0 = (const float*)d_in[11];
    const float* Wm1 = (const float*)d_in[12]; const float* bm1 = (const float*)d_in[13];
    const float* Wm2 = (const float*)d_in[14]; const float* bm2 = (const float*)d_in[15];
    float* out = (float*)d_out;

    float *emb, *x1, *x2;
    __half *whi, *wlo;
    cudaGetSymbolAddress((void**)&emb,  g_emb);
    cudaGetSymbolAddress((void**)&x1,   g_x1);
    cudaGetSymbolAddress((void**)&x2,   g_x2);
    cudaGetSymbolAddress((void**)&whi,  g_whi);
    cudaGetSymbolAddress((void**)&wlo,  g_wlo);

    cudaFuncSetAttribute(k_gemm_mma<0>, cudaFuncAttributeMaxDynamicSharedMemorySize,
                         kMmaSmemBytes);
    cudaFuncSetAttribute(k_gemm_mma<1>, cudaFuncAttributeMaxDynamicSharedMemorySize,
                         kMmaSmemBytes);

    const int T = 256;
    int nBlkN = (kN + T - 1) / T;           // 391
    int nBlkZ = (kG * kD + T - 1) / T;      // 1024
    int nBlkE = (kE + T - 1) / T;           // 6250
    int nBlkWarpN = (kN * 32 + T - 1) / T;  // 12500
    int nBlkTc = (kN + 127) / 128;          // 782
    int nBlkH = (kN * kD / 4 + T - 1) / T;  // 12500

    k_zero<<<nBlkZ, T>>>();
    k_degrees<<<nBlkE, T>>>(src, dst);
    k_scan1<<<kScanBlocks, 1024>>>();
    k_scan_tops<<<1, 1024>>>();
    k_scan_add_inv<<<nBlkN, T>>>(gids);
    k_scatter<<<nBlkE, T>>>(src, dst);
    k_wsplit_all<<<192, T>>>(W0, W1, W2);
    k_f2h<<<nBlkH, T>>>(feats);

    k_gather<<<nBlkWarpN, T>>>();
    k_gemm_mma<0><<<nBlkTc, T, kMmaSmemBytes>>>(whi + 0 * kD * kD, wlo + 0 * kD * kD,
                                                b0, gids, kN);
    k_gather<<<nBlkWarpN, T>>>();
    k_gemm_mma<0><<<nBlkTc, T, kMmaSmemBytes>>>(whi + 1 * kD * kD, wlo + 1 * kD * kD,
                                                b1, gids, kN);
    k_gather<<<nBlkWarpN, T>>>();
    k_gemm_mma<1><<<nBlkTc, T, kMmaSmemBytes>>>(whi + 2 * kD * kD, wlo + 2 * kD * kD,
                                                b2, gids, kN);

    k_mlp<true><<<(kG / 8) * 512 / T, T>>>(emb, Wm0, bm0, x1, 128, 512);
    k_mlp<false><<<(kG / 8) * 256 / T, T>>>(x1, Wm1, bm1, x2, 512, 256);
    k_final<<<(kG * 32) / T, T>>>(x2, Wm2, bm2, out);
}